// round 4
// baseline (speedup 1.0000x reference)
#include <cuda_runtime.h>

#define NN 100000
#define NE 1600000
#define C_IN 64
#define C_HID 128
#define NG 64
#define NC 10

// ---------------- scratch (__device__ globals; no allocations) ----------------
static __device__ __align__(16) int   g_degi[NN];      // in-degree (excl. self loop)
static __device__ __align__(16) int   g_off[NN];       // CSR row offsets (exclusive)
static __device__ __align__(16) int   g_cur[NN];       // fill cursors
static __device__ __align__(16) float g_dinv[NN];
static __device__ __align__(16) int   g_src[NE];
static __device__ __align__(16) int   g_dst[NE];
static __device__ __align__(16) int   g_csrc[NE];      // CSR: src sorted by dst
static __device__ __align__(16) float g_cnorm[NE];     // CSR: edge norm sorted by dst
static __device__ __align__(16) float g_bufA[(size_t)NN * C_HID];   // 51.2 MB
static __device__ __align__(16) float g_bufB[(size_t)NN * C_HID];   // 51.2 MB
static __device__ __align__(16) float g_pooled[NG * C_HID];
static __device__ __align__(16) float g_cnt[NG];
static __device__ int g_is64;   // 1 if index tensors are int64, 0 if int32

__device__ __forceinline__ float* bufsel(int s) { return s == 0 ? g_bufA : g_bufB; }
__device__ __forceinline__ const float* srcsel(const float* ext, int s) {
    return s < 0 ? ext : (const float*)bufsel(s);
}
__device__ __forceinline__ int read_idx(const void* p, long long i) {
    if (g_is64) return (int)((const long long*)p)[i];
    return ((const int*)p)[i];
}

// ---------------- packed fp32x2 helpers (Blackwell FFMA2) ----------------
__device__ __forceinline__ unsigned long long pack2(float lo, float hi) {
    unsigned long long r;
    asm("mov.b64 %0, {%1, %2};" : "=l"(r) : "f"(lo), "f"(hi));
    return r;
}
__device__ __forceinline__ float2 unpack2(unsigned long long v) {
    float2 f;
    asm("mov.b64 {%0, %1}, %2;" : "=f"(f.x), "=f"(f.y) : "l"(v));
    return f;
}
__device__ __forceinline__ unsigned long long fma2(unsigned long long a,
                                                   unsigned long long b,
                                                   unsigned long long c) {
    unsigned long long d;
    asm("fma.rn.f32x2 %0, %1, %2, %3;" : "=l"(d) : "l"(a), "l"(b), "l"(c));
    return d;
}

// ---------------- dtype detection ----------------
__global__ void k_detect(const void* __restrict__ ei) {
    if (threadIdx.x == 0) {
        const long long* p = (const long long*)ei;
        int ok64 = 1;
        for (int i = 0; i < 64; ++i) {
            long long v = p[i];
            if (v < 0 || v >= NN) { ok64 = 0; break; }
        }
        g_is64 = ok64;
    }
}

// ---------------- prep ----------------
__global__ void k_init() {
    int t = blockIdx.x * blockDim.x + threadIdx.x;
    if (t < NN) g_degi[t] = 0;
    if (t < NG * C_HID) g_pooled[t] = 0.0f;
    if (t < NG) g_cnt[t] = 0.0f;
}

__global__ void k_edge_prep(const void* __restrict__ ei) {
    int e = blockIdx.x * blockDim.x + threadIdx.x;
    if (e >= NE) return;
    int s = read_idx(ei, e);
    int d = read_idx(ei, (long long)NE + e);
    s = min(max(s, 0), NN - 1);   // defensive
    d = min(max(d, 0), NN - 1);
    g_src[e] = s;
    g_dst[e] = d;
    atomicAdd(&g_degi[d], 1);
}

// single-block exclusive scan over NN degrees; also dinv = rsqrt(deg+1)
__global__ __launch_bounds__(1024) void k_scan() {
    const int T = 1024;
    const int CH = (NN + T - 1) / T;   // 98
    int tid = threadIdx.x;
    int start = tid * CH;
    int end = min(start + CH, NN);
    int sum = 0;
    for (int i = start; i < end; ++i) sum += g_degi[i];

    int lane = tid & 31, wid = tid >> 5;
    int v = sum;
#pragma unroll
    for (int o = 1; o < 32; o <<= 1) {
        int t = __shfl_up_sync(0xFFFFFFFFu, v, o);
        if (lane >= o) v += t;
    }
    __shared__ int ws[32];
    if (lane == 31) ws[wid] = v;
    __syncthreads();
    if (wid == 0) {
        int w = ws[lane];
#pragma unroll
        for (int o = 1; o < 32; o <<= 1) {
            int t = __shfl_up_sync(0xFFFFFFFFu, w, o);
            if (lane >= o) w += t;
        }
        ws[lane] = w;
    }
    __syncthreads();
    int excl = v - sum + (wid > 0 ? ws[wid - 1] : 0);
    int run = excl;
    for (int i = start; i < end; ++i) {
        g_off[i] = run;
        g_cur[i] = run;
        run += g_degi[i];
        g_dinv[i] = rsqrtf((float)(g_degi[i] + 1));
    }
}

// fill CSR (src + norm) bucketed by dst
__global__ void k_csr_fill() {
    int e = blockIdx.x * blockDim.x + threadIdx.x;
    if (e >= NE) return;
    int s = g_src[e], d = g_dst[e];
    int pos = atomicAdd(&g_cur[d], 1);
    g_csrc[pos] = s;
    g_cnorm[pos] = g_dinv[s] * g_dinv[d];
}

// ---------------- aggregation (gather, CSR): one warp per node ----------------
// A[i] = dinv[i]^2 * H[i] + sum_e norm[e] * H[csrc[e]]
__global__ __launch_bounds__(256) void k_agg64(const float* __restrict__ ext, int ds) {
    const float* H = ext;
    float* A = bufsel(ds);
    int lane = threadIdx.x & 31;
    int node = (blockIdx.x * blockDim.x + threadIdx.x) >> 5;
    if (node >= NN) return;
    float di = g_dinv[node];
    float sw = di * di;
    float2 acc = *(const float2*)&H[(size_t)node * 64 + lane * 2];
    acc.x *= sw; acc.y *= sw;
    int beg = g_off[node];
    int cnt = g_degi[node];
    int k = 0;
    for (; k + 2 <= cnt; k += 2) {
        int s0 = g_csrc[beg + k];
        int s1 = g_csrc[beg + k + 1];
        float w0 = g_cnorm[beg + k];
        float w1 = g_cnorm[beg + k + 1];
        float2 v0 = *(const float2*)&H[(size_t)s0 * 64 + lane * 2];
        float2 v1 = *(const float2*)&H[(size_t)s1 * 64 + lane * 2];
        acc.x += w0 * v0.x + w1 * v1.x;
        acc.y += w0 * v0.y + w1 * v1.y;
    }
    if (k < cnt) {
        int s0 = g_csrc[beg + k];
        float w0 = g_cnorm[beg + k];
        float2 v0 = *(const float2*)&H[(size_t)s0 * 64 + lane * 2];
        acc.x += w0 * v0.x;
        acc.y += w0 * v0.y;
    }
    *(float2*)&A[(size_t)node * 64 + lane * 2] = acc;
}

__global__ __launch_bounds__(256) void k_agg128(int ss, int ds) {
    const float* H = (const float*)bufsel(ss);
    float* A = bufsel(ds);
    int lane = threadIdx.x & 31;
    int node = (blockIdx.x * blockDim.x + threadIdx.x) >> 5;
    if (node >= NN) return;
    float di = g_dinv[node];
    float sw = di * di;
    float4 acc = *(const float4*)&H[(size_t)node * 128 + lane * 4];
    acc.x *= sw; acc.y *= sw; acc.z *= sw; acc.w *= sw;
    int beg = g_off[node];
    int cnt = g_degi[node];
    int k = 0;
    for (; k + 2 <= cnt; k += 2) {
        int s0 = g_csrc[beg + k];
        int s1 = g_csrc[beg + k + 1];
        float w0 = g_cnorm[beg + k];
        float w1 = g_cnorm[beg + k + 1];
        float4 v0 = *(const float4*)&H[(size_t)s0 * 128 + lane * 4];
        float4 v1 = *(const float4*)&H[(size_t)s1 * 128 + lane * 4];
        acc.x += w0 * v0.x + w1 * v1.x;
        acc.y += w0 * v0.y + w1 * v1.y;
        acc.z += w0 * v0.z + w1 * v1.z;
        acc.w += w0 * v0.w + w1 * v1.w;
    }
    if (k < cnt) {
        int s0 = g_csrc[beg + k];
        float w0 = g_cnorm[beg + k];
        float4 v0 = *(const float4*)&H[(size_t)s0 * 128 + lane * 4];
        acc.x += w0 * v0.x;
        acc.y += w0 * v0.y;
        acc.z += w0 * v0.z;
        acc.w += w0 * v0.w;
    }
    *(float4*)&A[(size_t)node * 128 + lane * 4] = acc;
}

// ---------------- GEMM: Y[N x 128] = relu(X[N x K] @ W[K x 128] + b) ----------------
template<int K>
__global__ __launch_bounds__(256)
void k_gemm_bias_relu(const float* __restrict__ ext, int ss, int ds,
                      const float* __restrict__ W, const float* __restrict__ bias) {
    const float* X = srcsel(ext, ss);
    float* Y = bufsel(ds);

    __shared__ float As[64][33];
    __shared__ float Ws[32][128];

    const int tid = threadIdx.x;
    const int tx = tid & 15;       // col group: 8 cols
    const int ty = tid >> 4;       // row group: 4 rows
    const int row_base = blockIdx.x * 64;

    unsigned long long acc[4][4];
#pragma unroll
    for (int i = 0; i < 4; ++i)
#pragma unroll
        for (int j = 0; j < 4; ++j) acc[i][j] = 0ull;

    float bv[8];
#pragma unroll
    for (int j = 0; j < 8; ++j) bv[j] = __ldg(&bias[tx * 8 + j]);

    for (int k0 = 0; k0 < K; k0 += 32) {
#pragma unroll
        for (int it = 0; it < 8; ++it) {
            int i = tid + it * 256;
            int r = i >> 5, kk = i & 31;
            int grow = row_base + r;
            As[r][kk] = (grow < NN) ? X[(size_t)grow * K + (k0 + kk)] : 0.0f;
        }
#pragma unroll
        for (int it = 0; it < 16; ++it) {
            int i = tid + it * 256;
            int kk = i >> 7, cc = i & 127;
            Ws[kk][cc] = W[(size_t)(k0 + kk) * C_HID + cc];
        }
        __syncthreads();

#pragma unroll 8
        for (int kk = 0; kk < 32; ++kk) {
            float4 bA = *(const float4*)&Ws[kk][tx * 8];
            float4 bB = *(const float4*)&Ws[kk][tx * 8 + 4];
            unsigned long long bp0 = pack2(bA.x, bA.y);
            unsigned long long bp1 = pack2(bA.z, bA.w);
            unsigned long long bp2 = pack2(bB.x, bB.y);
            unsigned long long bp3 = pack2(bB.z, bB.w);
#pragma unroll
            for (int i = 0; i < 4; ++i) {
                float av = As[ty * 4 + i][kk];
                unsigned long long a2 = pack2(av, av);
                acc[i][0] = fma2(a2, bp0, acc[i][0]);
                acc[i][1] = fma2(a2, bp1, acc[i][1]);
                acc[i][2] = fma2(a2, bp2, acc[i][2]);
                acc[i][3] = fma2(a2, bp3, acc[i][3]);
            }
        }
        __syncthreads();
    }

#pragma unroll
    for (int i = 0; i < 4; ++i) {
        int grow = row_base + ty * 4 + i;
        if (grow < NN) {
            float2 r0 = unpack2(acc[i][0]);
            float2 r1 = unpack2(acc[i][1]);
            float2 r2 = unpack2(acc[i][2]);
            float2 r3 = unpack2(acc[i][3]);
            float4 o0, o1;
            o0.x = fmaxf(r0.x + bv[0], 0.0f);
            o0.y = fmaxf(r0.y + bv[1], 0.0f);
            o0.z = fmaxf(r1.x + bv[2], 0.0f);
            o0.w = fmaxf(r1.y + bv[3], 0.0f);
            o1.x = fmaxf(r2.x + bv[4], 0.0f);
            o1.y = fmaxf(r2.y + bv[5], 0.0f);
            o1.z = fmaxf(r3.x + bv[6], 0.0f);
            o1.w = fmaxf(r3.y + bv[7], 0.0f);
            float* yp = &Y[(size_t)grow * C_HID + tx * 8];
            *(float4*)yp = o0;
            *(float4*)(yp + 4) = o1;
        }
    }
}

// ---------------- global mean pool (batch is sorted) ----------------
#define POOL_CHUNK 256
__global__ void k_pool(int ss, const void* __restrict__ batch) {
    const float* H = (const float*)bufsel(ss);
    __shared__ int sb[POOL_CHUNK];
    int n0 = blockIdx.x * POOL_CHUNK;
    int c = threadIdx.x;  // 0..127
    for (int i = c; i < POOL_CHUNK; i += 128) {
        int n = n0 + i;
        int g = 0;
        if (n < NN) g = read_idx(batch, n);
        g = min(max(g, 0), NG - 1);
        sb[i] = g;
    }
    __syncthreads();
    int lim = NN - n0; if (lim > POOL_CHUNK) lim = POOL_CHUNK;
    if (lim <= 0) return;
    float acc = 0.0f;
    int g = sb[0];
    int cntloc = 0;
    for (int i = 0; i < lim; ++i) {
        int gb = sb[i];
        if (gb != g) {
            atomicAdd(&g_pooled[g * C_HID + c], acc);
            if (c == 0) atomicAdd(&g_cnt[g], (float)cntloc);
            g = gb; acc = 0.0f; cntloc = 0;
        }
        acc += H[(size_t)(n0 + i) * C_HID + c];
        cntloc++;
    }
    atomicAdd(&g_pooled[g * C_HID + c], acc);
    if (c == 0) atomicAdd(&g_cnt[g], (float)cntloc);
}

// ---------------- classifier head ----------------
__global__ void k_final(const float* __restrict__ Wc, const float* __restrict__ bc,
                        float* __restrict__ out) {
    int t = threadIdx.x;
    if (t >= NG * NC) return;
    int g = t / NC, c = t % NC;
    float inv = 1.0f / fmaxf(g_cnt[g], 1.0f);
    float s = 0.0f;
#pragma unroll 16
    for (int h = 0; h < C_HID; ++h)
        s += g_pooled[g * C_HID + h] * __ldg(&Wc[h * NC + c]);
    out[t] = s * inv + bc[c];
}

// ---------------- launch ----------------
extern "C" void kernel_launch(void* const* d_in, const int* in_sizes, int n_in,
                              void* d_out, int out_size) {
    const float* x = 0; const float* W1 = 0; const float* b1 = 0;
    const float* W2 = 0; const float* b2 = 0; const float* Wc = 0;
    const float* bc = 0; const void* ei = 0; const void* batch = 0;
    for (int i = 0; i < n_in; ++i) {
        int s = in_sizes[i];
        void* p = d_in[i];
        if      (s == NN * C_IN)     x  = (const float*)p;
        else if (s == C_IN * C_HID)  W1 = (const float*)p;
        else if (s == C_HID * C_HID) W2 = (const float*)p;
        else if (s == C_HID * NC)    Wc = (const float*)p;
        else if (s == NC)            bc = (const float*)p;
        else if (s == 2 * NE)        ei = p;
        else if (s == NN)            batch = p;
        else if (s == C_HID)         { if (!b1) b1 = (const float*)p; else b2 = (const float*)p; }
    }
    if (!b2) b2 = b1;
    float* out = (float*)d_out;
    (void)out_size;

    const int T = 256;
    const int WARPS_GRID = (NN * 32 + T - 1) / T;   // one warp per node

    // launches 0-4: probe + CSR build
    k_detect<<<1, 32>>>(ei);                          // 0
    k_init<<<(NN + T - 1) / T, T>>>();                // 1
    k_edge_prep<<<(NE + T - 1) / T, T>>>(ei);         // 2
    k_scan<<<1, 1024>>>();                            // 3
    k_csr_fill<<<(NE + T - 1) / T, T>>>();            // 4

    // layer 1: gather-aggregate x (64 ch) -> bufA, GEMM -> H1 in bufB
    k_agg64<<<WARPS_GRID, T>>>(x, 0);                 // 5  (profiled slot)
    k_gemm_bias_relu<C_IN><<<(NN + 63) / 64, T>>>(nullptr, 0, 1, W1, b1);

    // layer 2: gather-aggregate H1 (128 ch) -> bufA, GEMM -> H2 in bufB
    k_agg128<<<WARPS_GRID, T>>>(1, 0);
    k_gemm_bias_relu<C_HID><<<(NN + 63) / 64, T>>>(nullptr, 0, 1, W2, b2);

    // pool (H2 in bufB) + head
    k_pool<<<(NN + POOL_CHUNK - 1) / POOL_CHUNK, C_HID>>>(1, batch);
    k_final<<<1, 640>>>(Wc, bc, out);
}

// round 5
// speedup vs baseline: 1.4356x; 1.4356x over previous
#include <cuda_runtime.h>

#define NN 100000
#define NE 1600000
#define C_IN 64
#define C_HID 128
#define NG 64
#define NC 10
#define NBLK ((NN + 255) / 256)   // 391

// ---------------- scratch (__device__ globals; no allocations) ----------------
static __device__ __align__(16) int   g_degi[NN];      // in-degree (excl. self loop)
static __device__ __align__(16) int   g_off[NN];       // CSR row offsets (exclusive)
static __device__ __align__(16) int   g_cur[NN];       // fill cursors
static __device__ __align__(16) float g_dinv[NN];
static __device__ __align__(16) int   g_bsum[NBLK];
static __device__ __align__(16) int   g_boff[NBLK];
static __device__ __align__(16) int   g_src[NE];
static __device__ __align__(16) int   g_dst[NE];
static __device__ __align__(16) int   g_csrc[NE];      // CSR: src sorted by dst
static __device__ __align__(16) float g_cnorm[NE];     // CSR: edge norm sorted by dst
static __device__ __align__(16) float g_bufA[(size_t)NN * C_HID];   // 51.2 MB
static __device__ __align__(16) float g_bufB[(size_t)NN * C_HID];   // 51.2 MB
static __device__ __align__(16) float g_pooled[NG * C_HID];
static __device__ __align__(16) float g_cnt[NG];
static __device__ int g_is64;   // 1 if index tensors are int64, 0 if int32

__device__ __forceinline__ float* bufsel(int s) { return s == 0 ? g_bufA : g_bufB; }
__device__ __forceinline__ const float* srcsel(const float* ext, int s) {
    return s < 0 ? ext : (const float*)bufsel(s);
}
__device__ __forceinline__ int read_idx(const void* p, long long i) {
    if (g_is64) return (int)((const long long*)p)[i];
    return ((const int*)p)[i];
}

// ---------------- packed fp32x2 helpers (Blackwell FFMA2) ----------------
__device__ __forceinline__ unsigned long long pack2(float lo, float hi) {
    unsigned long long r;
    asm("mov.b64 %0, {%1, %2};" : "=l"(r) : "f"(lo), "f"(hi));
    return r;
}
__device__ __forceinline__ float2 unpack2(unsigned long long v) {
    float2 f;
    asm("mov.b64 {%0, %1}, %2;" : "=f"(f.x), "=f"(f.y) : "l"(v));
    return f;
}
__device__ __forceinline__ unsigned long long fma2(unsigned long long a,
                                                   unsigned long long b,
                                                   unsigned long long c) {
    unsigned long long d;
    asm("fma.rn.f32x2 %0, %1, %2, %3;" : "=l"(d) : "l"(a), "l"(b), "l"(c));
    return d;
}

// ---------------- dtype detection ----------------
__global__ void k_detect(const void* __restrict__ ei) {
    if (threadIdx.x == 0) {
        const long long* p = (const long long*)ei;
        int ok64 = 1;
        for (int i = 0; i < 64; ++i) {
            long long v = p[i];
            if (v < 0 || v >= NN) { ok64 = 0; break; }
        }
        g_is64 = ok64;
    }
}

// ---------------- prep ----------------
__global__ void k_init() {
    int t = blockIdx.x * blockDim.x + threadIdx.x;
    if (t < NN) g_degi[t] = 0;
    if (t < NG * C_HID) g_pooled[t] = 0.0f;
    if (t < NG) g_cnt[t] = 0.0f;
}

__global__ void k_edge_prep(const void* __restrict__ ei) {
    int e = blockIdx.x * blockDim.x + threadIdx.x;
    if (e >= NE) return;
    int s = read_idx(ei, e);
    int d = read_idx(ei, (long long)NE + e);
    s = min(max(s, 0), NN - 1);   // defensive
    d = min(max(d, 0), NN - 1);
    g_src[e] = s;
    g_dst[e] = d;
    atomicAdd(&g_degi[d], 1);
}

// ---- parallel 3-phase exclusive scan over g_degi ----
__global__ __launch_bounds__(256) void k_blocksum() {
    __shared__ int ws[8];
    int i = blockIdx.x * 256 + threadIdx.x;
    int v = (i < NN) ? g_degi[i] : 0;
    int lane = threadIdx.x & 31, wid = threadIdx.x >> 5;
#pragma unroll
    for (int o = 16; o > 0; o >>= 1) v += __shfl_down_sync(0xFFFFFFFFu, v, o);
    if (lane == 0) ws[wid] = v;
    __syncthreads();
    if (threadIdx.x == 0) {
        int s = 0;
#pragma unroll
        for (int w = 0; w < 8; ++w) s += ws[w];
        g_bsum[blockIdx.x] = s;
    }
}

__global__ __launch_bounds__(512) void k_bscan() {
    __shared__ int sh[512];
    int t = threadIdx.x;
    sh[t] = (t < NBLK) ? g_bsum[t] : 0;
    __syncthreads();
#pragma unroll
    for (int o = 1; o < 512; o <<= 1) {
        int v = (t >= o) ? sh[t - o] : 0;
        __syncthreads();
        sh[t] += v;
        __syncthreads();
    }
    if (t < NBLK) g_boff[t] = sh[t] - g_bsum[t];   // exclusive
}

__global__ __launch_bounds__(256) void k_offsets() {
    __shared__ int ws[8];
    int i = blockIdx.x * 256 + threadIdx.x;
    int deg = (i < NN) ? g_degi[i] : 0;
    int lane = threadIdx.x & 31, wid = threadIdx.x >> 5;
    int v = deg;
#pragma unroll
    for (int o = 1; o < 32; o <<= 1) {
        int t = __shfl_up_sync(0xFFFFFFFFu, v, o);
        if (lane >= o) v += t;
    }
    if (lane == 31) ws[wid] = v;
    __syncthreads();
    if (wid == 0 && lane < 8) {
        int w = ws[lane];
#pragma unroll
        for (int o = 1; o < 8; o <<= 1) {
            int t = __shfl_up_sync(0xFFu, w, o);
            if (lane >= o) w += t;
        }
        ws[lane] = w;
    }
    __syncthreads();
    int excl = v - deg + (wid > 0 ? ws[wid - 1] : 0) + g_boff[blockIdx.x];
    if (i < NN) {
        g_off[i] = excl;
        g_cur[i] = excl;
        g_dinv[i] = rsqrtf((float)(deg + 1));
    }
}

// fill CSR (src + norm) bucketed by dst
__global__ void k_csr_fill() {
    int e = blockIdx.x * blockDim.x + threadIdx.x;
    if (e >= NE) return;
    int s = g_src[e], d = g_dst[e];
    int pos = atomicAdd(&g_cur[d], 1);
    g_csrc[pos] = s;
    g_cnorm[pos] = g_dinv[s] * g_dinv[d];
}

// ---------------- aggregation (gather, CSR): one warp per node ----------------
// A[i] = dinv[i]^2 * H[i] + sum_e norm[e] * H[csrc[e]]
__global__ __launch_bounds__(256) void k_agg64(const float* __restrict__ ext, int ds) {
    const float* H = ext;
    float* A = bufsel(ds);
    int lane = threadIdx.x & 31;
    int node = (blockIdx.x * blockDim.x + threadIdx.x) >> 5;
    if (node >= NN) return;
    float di = g_dinv[node];
    float sw = di * di;
    float2 acc = *(const float2*)&H[(size_t)node * 64 + lane * 2];
    acc.x *= sw; acc.y *= sw;
    int beg = g_off[node];
    int cnt = g_degi[node];
    int k = 0;
    for (; k + 2 <= cnt; k += 2) {
        int s0 = g_csrc[beg + k];
        int s1 = g_csrc[beg + k + 1];
        float w0 = g_cnorm[beg + k];
        float w1 = g_cnorm[beg + k + 1];
        float2 v0 = *(const float2*)&H[(size_t)s0 * 64 + lane * 2];
        float2 v1 = *(const float2*)&H[(size_t)s1 * 64 + lane * 2];
        acc.x += w0 * v0.x + w1 * v1.x;
        acc.y += w0 * v0.y + w1 * v1.y;
    }
    if (k < cnt) {
        int s0 = g_csrc[beg + k];
        float w0 = g_cnorm[beg + k];
        float2 v0 = *(const float2*)&H[(size_t)s0 * 64 + lane * 2];
        acc.x += w0 * v0.x;
        acc.y += w0 * v0.y;
    }
    *(float2*)&A[(size_t)node * 64 + lane * 2] = acc;
}

__global__ __launch_bounds__(256) void k_agg128(int ss, int ds) {
    const float* H = (const float*)bufsel(ss);
    float* A = bufsel(ds);
    int lane = threadIdx.x & 31;
    int node = (blockIdx.x * blockDim.x + threadIdx.x) >> 5;
    if (node >= NN) return;
    float di = g_dinv[node];
    float sw = di * di;
    float4 acc = *(const float4*)&H[(size_t)node * 128 + lane * 4];
    acc.x *= sw; acc.y *= sw; acc.z *= sw; acc.w *= sw;
    int beg = g_off[node];
    int cnt = g_degi[node];
    int k = 0;
    for (; k + 2 <= cnt; k += 2) {
        int s0 = g_csrc[beg + k];
        int s1 = g_csrc[beg + k + 1];
        float w0 = g_cnorm[beg + k];
        float w1 = g_cnorm[beg + k + 1];
        float4 v0 = *(const float4*)&H[(size_t)s0 * 128 + lane * 4];
        float4 v1 = *(const float4*)&H[(size_t)s1 * 128 + lane * 4];
        acc.x += w0 * v0.x + w1 * v1.x;
        acc.y += w0 * v0.y + w1 * v1.y;
        acc.z += w0 * v0.z + w1 * v1.z;
        acc.w += w0 * v0.w + w1 * v1.w;
    }
    if (k < cnt) {
        int s0 = g_csrc[beg + k];
        float w0 = g_cnorm[beg + k];
        float4 v0 = *(const float4*)&H[(size_t)s0 * 128 + lane * 4];
        acc.x += w0 * v0.x;
        acc.y += w0 * v0.y;
        acc.z += w0 * v0.z;
        acc.w += w0 * v0.w;
    }
    *(float4*)&A[(size_t)node * 128 + lane * 4] = acc;
}

// ---------------- GEMM: Y[N x 128] = relu(X[N x K] @ W[K x 128] + b) ----------------
template<int K>
__global__ __launch_bounds__(256)
void k_gemm_bias_relu(const float* __restrict__ ext, int ss, int ds,
                      const float* __restrict__ W, const float* __restrict__ bias) {
    const float* X = srcsel(ext, ss);
    float* Y = bufsel(ds);

    __shared__ float As[64][33];
    __shared__ float Ws[32][128];

    const int tid = threadIdx.x;
    const int tx = tid & 15;       // col group: 8 cols
    const int ty = tid >> 4;       // row group: 4 rows
    const int row_base = blockIdx.x * 64;

    unsigned long long acc[4][4];
#pragma unroll
    for (int i = 0; i < 4; ++i)
#pragma unroll
        for (int j = 0; j < 4; ++j) acc[i][j] = 0ull;

    float bv[8];
#pragma unroll
    for (int j = 0; j < 8; ++j) bv[j] = __ldg(&bias[tx * 8 + j]);

    for (int k0 = 0; k0 < K; k0 += 32) {
#pragma unroll
        for (int it = 0; it < 8; ++it) {
            int i = tid + it * 256;
            int r = i >> 5, kk = i & 31;
            int grow = row_base + r;
            As[r][kk] = (grow < NN) ? X[(size_t)grow * K + (k0 + kk)] : 0.0f;
        }
#pragma unroll
        for (int it = 0; it < 16; ++it) {
            int i = tid + it * 256;
            int kk = i >> 7, cc = i & 127;
            Ws[kk][cc] = W[(size_t)(k0 + kk) * C_HID + cc];
        }
        __syncthreads();

#pragma unroll 8
        for (int kk = 0; kk < 32; ++kk) {
            float4 bA = *(const float4*)&Ws[kk][tx * 8];
            float4 bB = *(const float4*)&Ws[kk][tx * 8 + 4];
            unsigned long long bp0 = pack2(bA.x, bA.y);
            unsigned long long bp1 = pack2(bA.z, bA.w);
            unsigned long long bp2 = pack2(bB.x, bB.y);
            unsigned long long bp3 = pack2(bB.z, bB.w);
#pragma unroll
            for (int i = 0; i < 4; ++i) {
                float av = As[ty * 4 + i][kk];
                unsigned long long a2 = pack2(av, av);
                acc[i][0] = fma2(a2, bp0, acc[i][0]);
                acc[i][1] = fma2(a2, bp1, acc[i][1]);
                acc[i][2] = fma2(a2, bp2, acc[i][2]);
                acc[i][3] = fma2(a2, bp3, acc[i][3]);
            }
        }
        __syncthreads();
    }

#pragma unroll
    for (int i = 0; i < 4; ++i) {
        int grow = row_base + ty * 4 + i;
        if (grow < NN) {
            float2 r0 = unpack2(acc[i][0]);
            float2 r1 = unpack2(acc[i][1]);
            float2 r2 = unpack2(acc[i][2]);
            float2 r3 = unpack2(acc[i][3]);
            float4 o0, o1;
            o0.x = fmaxf(r0.x + bv[0], 0.0f);
            o0.y = fmaxf(r0.y + bv[1], 0.0f);
            o0.z = fmaxf(r1.x + bv[2], 0.0f);
            o0.w = fmaxf(r1.y + bv[3], 0.0f);
            o1.x = fmaxf(r2.x + bv[4], 0.0f);
            o1.y = fmaxf(r2.y + bv[5], 0.0f);
            o1.z = fmaxf(r3.x + bv[6], 0.0f);
            o1.w = fmaxf(r3.y + bv[7], 0.0f);
            float* yp = &Y[(size_t)grow * C_HID + tx * 8];
            *(float4*)yp = o0;
            *(float4*)(yp + 4) = o1;
        }
    }
}

// ---------------- global mean pool (batch is sorted) ----------------
#define POOL_CHUNK 256
__global__ void k_pool(int ss, const void* __restrict__ batch) {
    const float* H = (const float*)bufsel(ss);
    __shared__ int sb[POOL_CHUNK];
    int n0 = blockIdx.x * POOL_CHUNK;
    int c = threadIdx.x;  // 0..127
    for (int i = c; i < POOL_CHUNK; i += 128) {
        int n = n0 + i;
        int g = 0;
        if (n < NN) g = read_idx(batch, n);
        g = min(max(g, 0), NG - 1);
        sb[i] = g;
    }
    __syncthreads();
    int lim = NN - n0; if (lim > POOL_CHUNK) lim = POOL_CHUNK;
    if (lim <= 0) return;
    float acc = 0.0f;
    int g = sb[0];
    int cntloc = 0;
    for (int i = 0; i < lim; ++i) {
        int gb = sb[i];
        if (gb != g) {
            atomicAdd(&g_pooled[g * C_HID + c], acc);
            if (c == 0) atomicAdd(&g_cnt[g], (float)cntloc);
            g = gb; acc = 0.0f; cntloc = 0;
        }
        acc += H[(size_t)(n0 + i) * C_HID + c];
        cntloc++;
    }
    atomicAdd(&g_pooled[g * C_HID + c], acc);
    if (c == 0) atomicAdd(&g_cnt[g], (float)cntloc);
}

// ---------------- classifier head ----------------
__global__ void k_final(const float* __restrict__ Wc, const float* __restrict__ bc,
                        float* __restrict__ out) {
    int t = threadIdx.x;
    if (t >= NG * NC) return;
    int g = t / NC, c = t % NC;
    float inv = 1.0f / fmaxf(g_cnt[g], 1.0f);
    float s = 0.0f;
#pragma unroll 16
    for (int h = 0; h < C_HID; ++h)
        s += g_pooled[g * C_HID + h] * __ldg(&Wc[h * NC + c]);
    out[t] = s * inv + bc[c];
}

// ---------------- launch ----------------
extern "C" void kernel_launch(void* const* d_in, const int* in_sizes, int n_in,
                              void* d_out, int out_size) {
    const float* x = 0; const float* W1 = 0; const float* b1 = 0;
    const float* W2 = 0; const float* b2 = 0; const float* Wc = 0;
    const float* bc = 0; const void* ei = 0; const void* batch = 0;
    for (int i = 0; i < n_in; ++i) {
        int s = in_sizes[i];
        void* p = d_in[i];
        if      (s == NN * C_IN)     x  = (const float*)p;
        else if (s == C_IN * C_HID)  W1 = (const float*)p;
        else if (s == C_HID * C_HID) W2 = (const float*)p;
        else if (s == C_HID * NC)    Wc = (const float*)p;
        else if (s == NC)            bc = (const float*)p;
        else if (s == 2 * NE)        ei = p;
        else if (s == NN)            batch = p;
        else if (s == C_HID)         { if (!b1) b1 = (const float*)p; else b2 = (const float*)p; }
    }
    if (!b2) b2 = b1;
    float* out = (float*)d_out;
    (void)out_size;

    const int T = 256;
    const int WARPS_GRID = (NN * 32 + T - 1) / T;   // one warp per node

    // prep + CSR build (launches 0-6)
    k_detect<<<1, 32>>>(ei);                          // 0
    k_init<<<(NN + T - 1) / T, T>>>();                // 1
    k_edge_prep<<<(NE + T - 1) / T, T>>>(ei);         // 2
    k_blocksum<<<NBLK, 256>>>();                      // 3
    k_bscan<<<1, 512>>>();                            // 4
    k_offsets<<<NBLK, 256>>>();                       // 5
    k_csr_fill<<<(NE + T - 1) / T, T>>>();            // 6

    // layer 1: gather-aggregate x (64 ch) -> bufA, GEMM -> H1 in bufB
    k_agg64<<<WARPS_GRID, T>>>(x, 0);
    k_gemm_bias_relu<C_IN><<<(NN + 63) / 64, T>>>(nullptr, 0, 1, W1, b1);

    // layer 2: gather-aggregate H1 (128 ch) -> bufA, GEMM -> H2 in bufB
    k_agg128<<<WARPS_GRID, T>>>(1, 0);
    k_gemm_bias_relu<C_HID><<<(NN + 63) / 64, T>>>(nullptr, 0, 1, W2, b2);

    // pool (H2 in bufB) + head
    k_pool<<<(NN + POOL_CHUNK - 1) / POOL_CHUNK, C_HID>>>(1, batch);
    k_final<<<1, 640>>>(Wc, bc, out);
}

// round 6
// speedup vs baseline: 1.6640x; 1.1591x over previous
#include <cuda_runtime.h>

#define NN 100000
#define NE 1600000
#define C_IN 64
#define C_HID 128
#define NG 64
#define NC 10
#define NBLK ((NN + 255) / 256)   // 391
#define NTILE ((NN + 63) / 64)    // 1563

// ---------------- scratch (__device__ globals; no allocations) ----------------
static __device__ __align__(16) int   g_degi[NN];      // in-degree (excl. self loop)
static __device__ __align__(16) int   g_off[NN];       // CSR row offsets (exclusive)
static __device__ __align__(16) int   g_cur[NN];       // fill cursors
static __device__ __align__(16) float g_dinv[NN];
static __device__ __align__(16) int   g_bsum[NBLK];
static __device__ __align__(16) int   g_boff[NBLK];
static __device__ __align__(16) int2  g_sd[NE];        // {src, dst} coalesced
static __device__ __align__(16) int2  g_edge[NE];      // CSR payload: {src, norm-bits}
static __device__ __align__(16) float g_h1[(size_t)NN * C_HID];  // 51.2 MB
static __device__ __align__(16) float g_pooled[NG * C_HID];
static __device__ __align__(16) float g_cnt[NG];
static __device__ int g_is64;   // 1 if index tensors are int64, 0 if int32

__device__ __forceinline__ int read_idx(const void* p, long long i) {
    if (g_is64) return (int)((const long long*)p)[i];
    return ((const int*)p)[i];
}

// ---------------- packed fp32x2 helpers (Blackwell FFMA2) ----------------
__device__ __forceinline__ unsigned long long pack2(float lo, float hi) {
    unsigned long long r;
    asm("mov.b64 %0, {%1, %2};" : "=l"(r) : "f"(lo), "f"(hi));
    return r;
}
__device__ __forceinline__ float2 unpack2(unsigned long long v) {
    float2 f;
    asm("mov.b64 {%0, %1}, %2;" : "=f"(f.x), "=f"(f.y) : "l"(v));
    return f;
}
__device__ __forceinline__ unsigned long long fma2(unsigned long long a,
                                                   unsigned long long b,
                                                   unsigned long long c) {
    unsigned long long d;
    asm("fma.rn.f32x2 %0, %1, %2, %3;" : "=l"(d) : "l"(a), "l"(b), "l"(c));
    return d;
}

// ---------------- dtype detection ----------------
__global__ void k_detect(const void* __restrict__ ei) {
    if (threadIdx.x == 0) {
        const long long* p = (const long long*)ei;
        int ok64 = 1;
        for (int i = 0; i < 64; ++i) {
            long long v = p[i];
            if (v < 0 || v >= NN) { ok64 = 0; break; }
        }
        g_is64 = ok64;
    }
}

// ---------------- prep ----------------
__global__ void k_init() {
    int t = blockIdx.x * blockDim.x + threadIdx.x;
    if (t < NN) g_degi[t] = 0;
    if (t < NG * C_HID) g_pooled[t] = 0.0f;
    if (t < NG) g_cnt[t] = 0.0f;
}

__global__ void k_edge_prep(const void* __restrict__ ei) {
    int e = blockIdx.x * blockDim.x + threadIdx.x;
    if (e >= NE) return;
    int s = read_idx(ei, e);
    int d = read_idx(ei, (long long)NE + e);
    s = min(max(s, 0), NN - 1);   // defensive
    d = min(max(d, 0), NN - 1);
    g_sd[e] = make_int2(s, d);
    atomicAdd(&g_degi[d], 1);
}

// ---- parallel 3-phase exclusive scan over g_degi ----
__global__ __launch_bounds__(256) void k_blocksum() {
    __shared__ int ws[8];
    int i = blockIdx.x * 256 + threadIdx.x;
    int v = (i < NN) ? g_degi[i] : 0;
    int lane = threadIdx.x & 31, wid = threadIdx.x >> 5;
#pragma unroll
    for (int o = 16; o > 0; o >>= 1) v += __shfl_down_sync(0xFFFFFFFFu, v, o);
    if (lane == 0) ws[wid] = v;
    __syncthreads();
    if (threadIdx.x == 0) {
        int s = 0;
#pragma unroll
        for (int w = 0; w < 8; ++w) s += ws[w];
        g_bsum[blockIdx.x] = s;
    }
}

__global__ __launch_bounds__(512) void k_bscan() {
    __shared__ int sh[512];
    int t = threadIdx.x;
    sh[t] = (t < NBLK) ? g_bsum[t] : 0;
    __syncthreads();
#pragma unroll
    for (int o = 1; o < 512; o <<= 1) {
        int v = (t >= o) ? sh[t - o] : 0;
        __syncthreads();
        sh[t] += v;
        __syncthreads();
    }
    if (t < NBLK) g_boff[t] = sh[t] - g_bsum[t];   // exclusive
}

__global__ __launch_bounds__(256) void k_offsets() {
    __shared__ int ws[8];
    int i = blockIdx.x * 256 + threadIdx.x;
    int deg = (i < NN) ? g_degi[i] : 0;
    int lane = threadIdx.x & 31, wid = threadIdx.x >> 5;
    int v = deg;
#pragma unroll
    for (int o = 1; o < 32; o <<= 1) {
        int t = __shfl_up_sync(0xFFFFFFFFu, v, o);
        if (lane >= o) v += t;
    }
    if (lane == 31) ws[wid] = v;
    __syncthreads();
    if (wid == 0 && lane < 8) {
        int w = ws[lane];
#pragma unroll
        for (int o = 1; o < 8; o <<= 1) {
            int t = __shfl_up_sync(0xFFu, w, o);
            if (lane >= o) w += t;
        }
        ws[lane] = w;
    }
    __syncthreads();
    int excl = v - deg + (wid > 0 ? ws[wid - 1] : 0) + g_boff[blockIdx.x];
    if (i < NN) {
        g_off[i] = excl;
        g_cur[i] = excl;
        g_dinv[i] = rsqrtf((float)(deg + 1));
    }
}

// fill CSR payload {src, norm} bucketed by dst — single 8B scattered store
__global__ void k_csr_fill() {
    int e = blockIdx.x * blockDim.x + threadIdx.x;
    if (e >= NE) return;
    int2 sd = g_sd[e];
    int pos = atomicAdd(&g_cur[sd.y], 1);
    float nrm = g_dinv[sd.x] * g_dinv[sd.y];
    g_edge[pos] = make_int2(sd.x, __float_as_int(nrm));
}

// ---------------- fused layer 1: gather-agg(x,64) + GEMM W1 + bias + relu -> H1 ----------------
__global__ __launch_bounds__(256)
void k_fused1(const float* __restrict__ X, const float* __restrict__ W,
              const float* __restrict__ bias) {
    __shared__ float As[64][65];     // aggregated inputs (stride 65: 2-way conflict max)
    __shared__ float Ws[32][128];

    const int tid = threadIdx.x;
    const int lane = tid & 31;
    const int w = tid >> 5;          // warp 0..7
    const int node_base = blockIdx.x * 64;

    // phase 1: warp-per-node gather aggregation, K=64 (lane: 2 channels)
    for (int j = w; j < 64; j += 8) {
        int node = node_base + j;
        if (node < NN) {
            float di = g_dinv[node];
            float sw = di * di;
            float2 acc = *(const float2*)&X[(size_t)node * 64 + lane * 2];
            acc.x *= sw; acc.y *= sw;
            int beg = g_off[node];
            int cnt = g_degi[node];
            int k = 0;
            for (; k + 2 <= cnt; k += 2) {
                int2 e0 = g_edge[beg + k];
                int2 e1 = g_edge[beg + k + 1];
                float w0 = __int_as_float(e0.y);
                float w1 = __int_as_float(e1.y);
                float2 v0 = *(const float2*)&X[(size_t)e0.x * 64 + lane * 2];
                float2 v1 = *(const float2*)&X[(size_t)e1.x * 64 + lane * 2];
                acc.x += w0 * v0.x + w1 * v1.x;
                acc.y += w0 * v0.y + w1 * v1.y;
            }
            if (k < cnt) {
                int2 e0 = g_edge[beg + k];
                float w0 = __int_as_float(e0.y);
                float2 v0 = *(const float2*)&X[(size_t)e0.x * 64 + lane * 2];
                acc.x += w0 * v0.x;
                acc.y += w0 * v0.y;
            }
            As[j][lane * 2] = acc.x;
            As[j][lane * 2 + 1] = acc.y;
        } else {
            As[j][lane * 2] = 0.0f;
            As[j][lane * 2 + 1] = 0.0f;
        }
    }
    __syncthreads();

    // phase 2: GEMM (64x64) x (64x128), f32x2 accumulators
    const int tx = tid & 15;
    const int ty = tid >> 4;
    unsigned long long acc[4][4];
#pragma unroll
    for (int i = 0; i < 4; ++i)
#pragma unroll
        for (int jj = 0; jj < 4; ++jj) acc[i][jj] = 0ull;

    float bv[8];
#pragma unroll
    for (int jj = 0; jj < 8; ++jj) bv[jj] = __ldg(&bias[tx * 8 + jj]);

#pragma unroll
    for (int k0 = 0; k0 < 64; k0 += 32) {
#pragma unroll
        for (int it = 0; it < 16; ++it) {
            int i = tid + it * 256;
            int kk = i >> 7, cc = i & 127;
            Ws[kk][cc] = W[(size_t)(k0 + kk) * C_HID + cc];
        }
        __syncthreads();
#pragma unroll 8
        for (int kk = 0; kk < 32; ++kk) {
            float4 bA = *(const float4*)&Ws[kk][tx * 8];
            float4 bB = *(const float4*)&Ws[kk][tx * 8 + 4];
            unsigned long long bp0 = pack2(bA.x, bA.y);
            unsigned long long bp1 = pack2(bA.z, bA.w);
            unsigned long long bp2 = pack2(bB.x, bB.y);
            unsigned long long bp3 = pack2(bB.z, bB.w);
#pragma unroll
            for (int i = 0; i < 4; ++i) {
                float av = As[ty * 4 + i][k0 + kk];
                unsigned long long a2 = pack2(av, av);
                acc[i][0] = fma2(a2, bp0, acc[i][0]);
                acc[i][1] = fma2(a2, bp1, acc[i][1]);
                acc[i][2] = fma2(a2, bp2, acc[i][2]);
                acc[i][3] = fma2(a2, bp3, acc[i][3]);
            }
        }
        __syncthreads();
    }

#pragma unroll
    for (int i = 0; i < 4; ++i) {
        int grow = node_base + ty * 4 + i;
        if (grow < NN) {
            float2 r0 = unpack2(acc[i][0]);
            float2 r1 = unpack2(acc[i][1]);
            float2 r2 = unpack2(acc[i][2]);
            float2 r3 = unpack2(acc[i][3]);
            float4 o0, o1;
            o0.x = fmaxf(r0.x + bv[0], 0.0f);
            o0.y = fmaxf(r0.y + bv[1], 0.0f);
            o0.z = fmaxf(r1.x + bv[2], 0.0f);
            o0.w = fmaxf(r1.y + bv[3], 0.0f);
            o1.x = fmaxf(r2.x + bv[4], 0.0f);
            o1.y = fmaxf(r2.y + bv[5], 0.0f);
            o1.z = fmaxf(r3.x + bv[6], 0.0f);
            o1.w = fmaxf(r3.y + bv[7], 0.0f);
            float* yp = &g_h1[(size_t)grow * C_HID + tx * 8];
            *(float4*)yp = o0;
            *(float4*)(yp + 4) = o1;
        }
    }
}

// ---------------- fused layer 2: gather-agg(H1,128) + GEMM W2 + relu + mean-pool ----------------
// dynamic smem: As[64][129] | Ws2[128][128] | sbat[64]
#define F2_AS   (64 * 129)
#define F2_WS   (128 * 128)
#define F2_SMEM ((F2_AS + F2_WS) * 4 + 64 * 4)

__global__ __launch_bounds__(256)
void k_fused2(const float* __restrict__ W, const float* __restrict__ bias,
              const void* __restrict__ batch) {
    extern __shared__ float sm[];
    float* As = sm;                    // [64][129]
    float* Ws = sm + F2_AS;            // [128][128]
    int*   sbat = (int*)(Ws + F2_WS);  // [64]

    const int tid = threadIdx.x;
    const int lane = tid & 31;
    const int w = tid >> 5;
    const int node_base = blockIdx.x * 64;
    const int lim = min(64, NN - node_base);

    // load batch ids for this tile
    if (tid < 64) {
        int n = node_base + tid;
        int g = 0;
        if (n < NN) g = read_idx(batch, n);
        sbat[tid] = min(max(g, 0), NG - 1);
    }

    // load full W2 into smem (coalesced float4)
#pragma unroll
    for (int it = 0; it < 16; ++it) {
        int i4 = tid + it * 256;       // float4 index, 4096 total
        ((float4*)Ws)[i4] = ((const float4*)W)[i4];
    }

    // phase 1: warp-per-node gather aggregation, K=128 (lane: 4 channels)
    for (int j = w; j < 64; j += 8) {
        int node = node_base + j;
        float* row = &As[j * 129];
        if (node < NN) {
            float di = g_dinv[node];
            float sw = di * di;
            float4 acc = *(const float4*)&g_h1[(size_t)node * 128 + lane * 4];
            acc.x *= sw; acc.y *= sw; acc.z *= sw; acc.w *= sw;
            int beg = g_off[node];
            int cnt = g_degi[node];
            int k = 0;
            for (; k + 2 <= cnt; k += 2) {
                int2 e0 = g_edge[beg + k];
                int2 e1 = g_edge[beg + k + 1];
                float w0 = __int_as_float(e0.y);
                float w1 = __int_as_float(e1.y);
                float4 v0 = *(const float4*)&g_h1[(size_t)e0.x * 128 + lane * 4];
                float4 v1 = *(const float4*)&g_h1[(size_t)e1.x * 128 + lane * 4];
                acc.x += w0 * v0.x + w1 * v1.x;
                acc.y += w0 * v0.y + w1 * v1.y;
                acc.z += w0 * v0.z + w1 * v1.z;
                acc.w += w0 * v0.w + w1 * v1.w;
            }
            if (k < cnt) {
                int2 e0 = g_edge[beg + k];
                float w0 = __int_as_float(e0.y);
                float4 v0 = *(const float4*)&g_h1[(size_t)e0.x * 128 + lane * 4];
                acc.x += w0 * v0.x;
                acc.y += w0 * v0.y;
                acc.z += w0 * v0.z;
                acc.w += w0 * v0.w;
            }
            row[lane * 4]     = acc.x;
            row[lane * 4 + 1] = acc.y;
            row[lane * 4 + 2] = acc.z;
            row[lane * 4 + 3] = acc.w;
        } else {
            row[lane * 4]     = 0.0f;
            row[lane * 4 + 1] = 0.0f;
            row[lane * 4 + 2] = 0.0f;
            row[lane * 4 + 3] = 0.0f;
        }
    }
    __syncthreads();

    // phase 2: GEMM (64x128) x (128x128)
    const int tx = tid & 15;
    const int ty = tid >> 4;
    unsigned long long acc[4][4];
#pragma unroll
    for (int i = 0; i < 4; ++i)
#pragma unroll
        for (int jj = 0; jj < 4; ++jj) acc[i][jj] = 0ull;

    float bv[8];
#pragma unroll
    for (int jj = 0; jj < 8; ++jj) bv[jj] = __ldg(&bias[tx * 8 + jj]);

#pragma unroll 8
    for (int kk = 0; kk < 128; ++kk) {
        float4 bA = *(const float4*)&Ws[kk * 128 + tx * 8];
        float4 bB = *(const float4*)&Ws[kk * 128 + tx * 8 + 4];
        unsigned long long bp0 = pack2(bA.x, bA.y);
        unsigned long long bp1 = pack2(bA.z, bA.w);
        unsigned long long bp2 = pack2(bB.x, bB.y);
        unsigned long long bp3 = pack2(bB.z, bB.w);
#pragma unroll
        for (int i = 0; i < 4; ++i) {
            float av = As[(ty * 4 + i) * 129 + kk];
            unsigned long long a2 = pack2(av, av);
            acc[i][0] = fma2(a2, bp0, acc[i][0]);
            acc[i][1] = fma2(a2, bp1, acc[i][1]);
            acc[i][2] = fma2(a2, bp2, acc[i][2]);
            acc[i][3] = fma2(a2, bp3, acc[i][3]);
        }
    }
    __syncthreads();

    // phase 3: relu -> smem (overwrite As), then per-column pooled reduction
#pragma unroll
    for (int i = 0; i < 4; ++i) {
        int r = ty * 4 + i;
        float2 r0 = unpack2(acc[i][0]);
        float2 r1 = unpack2(acc[i][1]);
        float2 r2 = unpack2(acc[i][2]);
        float2 r3 = unpack2(acc[i][3]);
        float* rp = &As[r * 129 + tx * 8];
        rp[0] = fmaxf(r0.x + bv[0], 0.0f);
        rp[1] = fmaxf(r0.y + bv[1], 0.0f);
        rp[2] = fmaxf(r1.x + bv[2], 0.0f);
        rp[3] = fmaxf(r1.y + bv[3], 0.0f);
        rp[4] = fmaxf(r2.x + bv[4], 0.0f);
        rp[5] = fmaxf(r2.y + bv[5], 0.0f);
        rp[6] = fmaxf(r3.x + bv[6], 0.0f);
        rp[7] = fmaxf(r3.y + bv[7], 0.0f);
    }
    __syncthreads();

    if (tid < 128 && lim > 0) {
        int c = tid;
        float accp = 0.0f;
        int g = sbat[0];
        for (int r = 0; r < lim; ++r) {
            int gb = sbat[r];
            if (gb != g) {
                atomicAdd(&g_pooled[g * C_HID + c], accp);
                g = gb; accp = 0.0f;
            }
            accp += As[r * 129 + c];
        }
        atomicAdd(&g_pooled[g * C_HID + c], accp);
    }
}

// ---------------- graph-size histogram ----------------
__global__ __launch_bounds__(256) void k_cnt(const void* __restrict__ batch) {
    __shared__ int h[NG];
    if (threadIdx.x < NG) h[threadIdx.x] = 0;
    __syncthreads();
    int n = blockIdx.x * 256 + threadIdx.x;
    if (n < NN) {
        int g = read_idx(batch, n);
        g = min(max(g, 0), NG - 1);
        atomicAdd(&h[g], 1);
    }
    __syncthreads();
    if (threadIdx.x < NG && h[threadIdx.x] > 0)
        atomicAdd(&g_cnt[threadIdx.x], (float)h[threadIdx.x]);
}

// ---------------- classifier head ----------------
__global__ void k_final(const float* __restrict__ Wc, const float* __restrict__ bc,
                        float* __restrict__ out) {
    int t = threadIdx.x;
    if (t >= NG * NC) return;
    int g = t / NC, c = t % NC;
    float inv = 1.0f / fmaxf(g_cnt[g], 1.0f);
    float s = 0.0f;
#pragma unroll 16
    for (int h = 0; h < C_HID; ++h)
        s += g_pooled[g * C_HID + h] * __ldg(&Wc[h * NC + c]);
    out[t] = s * inv + bc[c];
}

// ---------------- launch ----------------
extern "C" void kernel_launch(void* const* d_in, const int* in_sizes, int n_in,
                              void* d_out, int out_size) {
    const float* x = 0; const float* W1 = 0; const float* b1 = 0;
    const float* W2 = 0; const float* b2 = 0; const float* Wc = 0;
    const float* bc = 0; const void* ei = 0; const void* batch = 0;
    for (int i = 0; i < n_in; ++i) {
        int s = in_sizes[i];
        void* p = d_in[i];
        if      (s == NN * C_IN)     x  = (const float*)p;
        else if (s == C_IN * C_HID)  W1 = (const float*)p;
        else if (s == C_HID * C_HID) W2 = (const float*)p;
        else if (s == C_HID * NC)    Wc = (const float*)p;
        else if (s == NC)            bc = (const float*)p;
        else if (s == 2 * NE)        ei = p;
        else if (s == NN)            batch = p;
        else if (s == C_HID)         { if (!b1) b1 = (const float*)p; else b2 = (const float*)p; }
    }
    if (!b2) b2 = b1;
    float* out = (float*)d_out;
    (void)out_size;

    static int attr_done = 0;
    if (!attr_done) {
        cudaFuncSetAttribute(k_fused2, cudaFuncAttributeMaxDynamicSharedMemorySize, F2_SMEM);
        attr_done = 1;
    }

    const int T = 256;

    // prep + CSR build
    k_detect<<<1, 32>>>(ei);                          // 0
    k_init<<<NBLK, T>>>();                            // 1
    k_edge_prep<<<(NE + T - 1) / T, T>>>(ei);         // 2
    k_blocksum<<<NBLK, T>>>();                        // 3
    k_bscan<<<1, 512>>>();                            // 4
    k_offsets<<<NBLK, T>>>();                         // 5
    k_csr_fill<<<(NE + T - 1) / T, T>>>();            // 6
    k_cnt<<<NBLK, T>>>(batch);                        // 7

    // fused layers
    k_fused1<<<NTILE, T>>>(x, W1, b1);                // 8
    k_fused2<<<NTILE, T, F2_SMEM>>>(W2, b2, batch);   // 9

    k_final<<<1, 640>>>(Wc, bc, out);                 // 10
}

// round 7
// speedup vs baseline: 1.9547x; 1.1747x over previous
#include <cuda_runtime.h>
#include <cuda_fp16.h>

#define NN 100000
#define NE 1600000
#define C_IN 64
#define C_HID 128
#define NG 64
#define NC 10
#define NBLK ((NN + 255) / 256)   // 391
#define NTILE ((NN + 63) / 64)    // 1563

// ---------------- scratch (__device__ globals; no allocations) ----------------
static __device__ __align__(16) int    g_degi[NN];
static __device__ __align__(16) int    g_off[NN];
static __device__ __align__(16) int    g_cur[NN];
static __device__ __align__(16) float  g_dinv[NN];
static __device__ __align__(16) int    g_bsum[NBLK];
static __device__ __align__(16) int    g_boff[NBLK];
static __device__ __align__(16) int2   g_edge[NE];     // CSR payload: {src, norm-bits}
static __device__ __align__(16) __half g_xh[(size_t)NN * C_IN];    // 12.8 MB
static __device__ __align__(16) __half g_h1h[(size_t)NN * C_HID];  // 25.6 MB
static __device__ __align__(16) float  g_pooled[NG * C_HID];
static __device__ __align__(16) float  g_cnt[NG];
static __device__ int g_is64;

__device__ __forceinline__ int read_idx(const void* p, long long i) {
    if (g_is64) return (int)((const long long*)p)[i];
    return ((const int*)p)[i];
}

// ---------------- packed fp32x2 helpers (Blackwell FFMA2) ----------------
__device__ __forceinline__ unsigned long long pack2(float lo, float hi) {
    unsigned long long r;
    asm("mov.b64 %0, {%1, %2};" : "=l"(r) : "f"(lo), "f"(hi));
    return r;
}
__device__ __forceinline__ float2 unpack2(unsigned long long v) {
    float2 f;
    asm("mov.b64 {%0, %1}, %2;" : "=f"(f.x), "=f"(f.y) : "l"(v));
    return f;
}
__device__ __forceinline__ unsigned long long fma2(unsigned long long a,
                                                   unsigned long long b,
                                                   unsigned long long c) {
    unsigned long long d;
    asm("fma.rn.f32x2 %0, %1, %2, %3;" : "=l"(d) : "l"(a), "l"(b), "l"(c));
    return d;
}
__device__ __forceinline__ float2 h2f(unsigned u) {
    __half2 h = *(__half2*)&u;
    return __half22float2(h);
}

// ---------------- dtype detection ----------------
__global__ void k_detect(const void* __restrict__ ei) {
    if (threadIdx.x == 0) {
        const long long* p = (const long long*)ei;
        int ok64 = 1;
        for (int i = 0; i < 64; ++i) {
            long long v = p[i];
            if (v < 0 || v >= NN) { ok64 = 0; break; }
        }
        g_is64 = ok64;
    }
}

// ---------------- prep ----------------
__global__ void k_init() {
    int t = blockIdx.x * blockDim.x + threadIdx.x;
    if (t < NN) g_degi[t] = 0;
    if (t < NG * C_HID) g_pooled[t] = 0.0f;
    if (t < NG) g_cnt[t] = 0.0f;
}

// x -> fp16 (4 floats per thread)
__global__ __launch_bounds__(256) void k_tohalf(const float* __restrict__ X) {
    int i = blockIdx.x * blockDim.x + threadIdx.x;
    const int total = NN * C_IN / 4;
    if (i >= total) return;
    float4 v = ((const float4*)X)[i];
    __half2 a = __floats2half2_rn(v.x, v.y);
    __half2 b = __floats2half2_rn(v.z, v.w);
    uint2 u;
    u.x = *(unsigned*)&a;
    u.y = *(unsigned*)&b;
    ((uint2*)g_xh)[i] = u;
}

__global__ void k_edge_prep(const void* __restrict__ ei) {
    int e = blockIdx.x * blockDim.x + threadIdx.x;
    if (e >= NE) return;
    int d = read_idx(ei, (long long)NE + e);
    d = min(max(d, 0), NN - 1);
    atomicAdd(&g_degi[d], 1);
}

// ---- parallel 3-phase exclusive scan over g_degi ----
__global__ __launch_bounds__(256) void k_blocksum() {
    __shared__ int ws[8];
    int i = blockIdx.x * 256 + threadIdx.x;
    int v = (i < NN) ? g_degi[i] : 0;
    int lane = threadIdx.x & 31, wid = threadIdx.x >> 5;
#pragma unroll
    for (int o = 16; o > 0; o >>= 1) v += __shfl_down_sync(0xFFFFFFFFu, v, o);
    if (lane == 0) ws[wid] = v;
    __syncthreads();
    if (threadIdx.x == 0) {
        int s = 0;
#pragma unroll
        for (int w = 0; w < 8; ++w) s += ws[w];
        g_bsum[blockIdx.x] = s;
    }
}

__global__ __launch_bounds__(512) void k_bscan() {
    __shared__ int sh[512];
    int t = threadIdx.x;
    sh[t] = (t < NBLK) ? g_bsum[t] : 0;
    __syncthreads();
#pragma unroll
    for (int o = 1; o < 512; o <<= 1) {
        int v = (t >= o) ? sh[t - o] : 0;
        __syncthreads();
        sh[t] += v;
        __syncthreads();
    }
    if (t < NBLK) g_boff[t] = sh[t] - g_bsum[t];   // exclusive
}

__global__ __launch_bounds__(256) void k_offsets() {
    __shared__ int ws[8];
    int i = blockIdx.x * 256 + threadIdx.x;
    int deg = (i < NN) ? g_degi[i] : 0;
    int lane = threadIdx.x & 31, wid = threadIdx.x >> 5;
    int v = deg;
#pragma unroll
    for (int o = 1; o < 32; o <<= 1) {
        int t = __shfl_up_sync(0xFFFFFFFFu, v, o);
        if (lane >= o) v += t;
    }
    if (lane == 31) ws[wid] = v;
    __syncthreads();
    if (wid == 0 && lane < 8) {
        int w = ws[lane];
#pragma unroll
        for (int o = 1; o < 8; o <<= 1) {
            int t = __shfl_up_sync(0xFFu, w, o);
            if (lane >= o) w += t;
        }
        ws[lane] = w;
    }
    __syncthreads();
    int excl = v - deg + (wid > 0 ? ws[wid - 1] : 0) + g_boff[blockIdx.x];
    if (i < NN) {
        g_off[i] = excl;
        g_cur[i] = excl;
        g_dinv[i] = rsqrtf((float)(deg + 1));
    }
}

// fill CSR payload {src, norm} bucketed by dst
__global__ void k_csr_fill(const void* __restrict__ ei) {
    int e = blockIdx.x * blockDim.x + threadIdx.x;
    if (e >= NE) return;
    int s = read_idx(ei, e);
    int d = read_idx(ei, (long long)NE + e);
    s = min(max(s, 0), NN - 1);
    d = min(max(d, 0), NN - 1);
    int pos = atomicAdd(&g_cur[d], 1);
    float nrm = g_dinv[s] * g_dinv[d];
    g_edge[pos] = make_int2(s, __float_as_int(nrm));
}

// ---------------- fused layer 1: gather-agg(x_h,64) + GEMM W1 + bias + relu -> H1(fp16) ----------------
__global__ __launch_bounds__(256)
void k_fused1(const float* __restrict__ W, const float* __restrict__ bias) {
    __shared__ float As[64][65];
    __shared__ float Ws[32][128];

    const int tid = threadIdx.x;
    const int lane = tid & 31;
    const int w = tid >> 5;
    const int node_base = blockIdx.x * 64;
    const unsigned* Xu = (const unsigned*)g_xh;   // half2 words; row = node*32

    // phase 1: warp-per-node gather aggregation (lane: 2 channels via one half2)
    for (int j = w; j < 64; j += 8) {
        int node = node_base + j;
        if (node < NN) {
            float di = g_dinv[node];
            float sw = di * di;
            float2 acc = h2f(Xu[node * 32 + lane]);
            acc.x *= sw; acc.y *= sw;
            int beg = g_off[node];
            int cnt = g_degi[node];
            int k = 0;
            for (; k + 2 <= cnt; k += 2) {
                int2 e0 = g_edge[beg + k];
                int2 e1 = g_edge[beg + k + 1];
                float w0 = __int_as_float(e0.y);
                float w1 = __int_as_float(e1.y);
                float2 v0 = h2f(Xu[e0.x * 32 + lane]);
                float2 v1 = h2f(Xu[e1.x * 32 + lane]);
                acc.x += w0 * v0.x + w1 * v1.x;
                acc.y += w0 * v0.y + w1 * v1.y;
            }
            if (k < cnt) {
                int2 e0 = g_edge[beg + k];
                float w0 = __int_as_float(e0.y);
                float2 v0 = h2f(Xu[e0.x * 32 + lane]);
                acc.x += w0 * v0.x;
                acc.y += w0 * v0.y;
            }
            As[j][lane * 2] = acc.x;
            As[j][lane * 2 + 1] = acc.y;
        } else {
            As[j][lane * 2] = 0.0f;
            As[j][lane * 2 + 1] = 0.0f;
        }
    }
    __syncthreads();

    // phase 2: GEMM (64x64) x (64x128)
    const int tx = tid & 15;
    const int ty = tid >> 4;
    unsigned long long acc[4][4];
#pragma unroll
    for (int i = 0; i < 4; ++i)
#pragma unroll
        for (int jj = 0; jj < 4; ++jj) acc[i][jj] = 0ull;

    float bv[8];
#pragma unroll
    for (int jj = 0; jj < 8; ++jj) bv[jj] = __ldg(&bias[tx * 8 + jj]);

#pragma unroll
    for (int k0 = 0; k0 < 64; k0 += 32) {
#pragma unroll
        for (int it = 0; it < 16; ++it) {
            int i = tid + it * 256;
            int kk = i >> 7, cc = i & 127;
            Ws[kk][cc] = W[(size_t)(k0 + kk) * C_HID + cc];
        }
        __syncthreads();
#pragma unroll 8
        for (int kk = 0; kk < 32; ++kk) {
            float4 bA = *(const float4*)&Ws[kk][tx * 8];
            float4 bB = *(const float4*)&Ws[kk][tx * 8 + 4];
            unsigned long long bp0 = pack2(bA.x, bA.y);
            unsigned long long bp1 = pack2(bA.z, bA.w);
            unsigned long long bp2 = pack2(bB.x, bB.y);
            unsigned long long bp3 = pack2(bB.z, bB.w);
#pragma unroll
            for (int i = 0; i < 4; ++i) {
                float av = As[ty * 4 + i][k0 + kk];
                unsigned long long a2 = pack2(av, av);
                acc[i][0] = fma2(a2, bp0, acc[i][0]);
                acc[i][1] = fma2(a2, bp1, acc[i][1]);
                acc[i][2] = fma2(a2, bp2, acc[i][2]);
                acc[i][3] = fma2(a2, bp3, acc[i][3]);
            }
        }
        __syncthreads();
    }

    // epilogue: bias + relu -> fp16 store (8 halves = one uint4)
#pragma unroll
    for (int i = 0; i < 4; ++i) {
        int grow = node_base + ty * 4 + i;
        if (grow < NN) {
            float2 r0 = unpack2(acc[i][0]);
            float2 r1 = unpack2(acc[i][1]);
            float2 r2 = unpack2(acc[i][2]);
            float2 r3 = unpack2(acc[i][3]);
            __half2 h0 = __floats2half2_rn(fmaxf(r0.x + bv[0], 0.0f), fmaxf(r0.y + bv[1], 0.0f));
            __half2 h1 = __floats2half2_rn(fmaxf(r1.x + bv[2], 0.0f), fmaxf(r1.y + bv[3], 0.0f));
            __half2 h2 = __floats2half2_rn(fmaxf(r2.x + bv[4], 0.0f), fmaxf(r2.y + bv[5], 0.0f));
            __half2 h3 = __floats2half2_rn(fmaxf(r3.x + bv[6], 0.0f), fmaxf(r3.y + bv[7], 0.0f));
            uint4 u;
            u.x = *(unsigned*)&h0;
            u.y = *(unsigned*)&h1;
            u.z = *(unsigned*)&h2;
            u.w = *(unsigned*)&h3;
            ((uint4*)g_h1h)[(size_t)grow * 16 + tx] = u;
        }
    }
}

// ---------------- fused layer 2: gather-agg(H1h,128) + GEMM W2(tiled) + relu + mean-pool ----------------
// dynamic smem: As[64][129] | Ws[32][128] | sbat[64]  ≈ 49.6 KB -> 4 CTAs/SM
#define F2_AS   (64 * 129)
#define F2_WS   (32 * 128)
#define F2_SMEM ((F2_AS + F2_WS) * 4 + 64 * 4)

__global__ __launch_bounds__(256)
void k_fused2(const float* __restrict__ W, const float* __restrict__ bias,
              const void* __restrict__ batch) {
    extern __shared__ float sm[];
    float* As = sm;                    // [64][129]
    float* Ws = sm + F2_AS;            // [32][128]
    int*   sbat = (int*)(Ws + F2_WS);  // [64]

    const int tid = threadIdx.x;
    const int lane = tid & 31;
    const int w = tid >> 5;
    const int node_base = blockIdx.x * 64;
    const int lim = min(64, NN - node_base);
    const uint2* Hu = (const uint2*)g_h1h;   // 4 halves per uint2; row = node*32

    if (tid < 64) {
        int n = node_base + tid;
        int g = 0;
        if (n < NN) g = read_idx(batch, n);
        sbat[tid] = min(max(g, 0), NG - 1);
    }

    // phase 1: warp-per-node gather aggregation (lane: 4 channels via one uint2)
    for (int j = w; j < 64; j += 8) {
        int node = node_base + j;
        float* row = &As[j * 129];
        if (node < NN) {
            float di = g_dinv[node];
            float sw = di * di;
            uint2 su = Hu[(size_t)node * 32 + lane];
            float2 sa = h2f(su.x), sb = h2f(su.y);
            float4 acc = make_float4(sa.x * sw, sa.y * sw, sb.x * sw, sb.y * sw);
            int beg = g_off[node];
            int cnt = g_degi[node];
            int k = 0;
            for (; k + 2 <= cnt; k += 2) {
                int2 e0 = g_edge[beg + k];
                int2 e1 = g_edge[beg + k + 1];
                float w0 = __int_as_float(e0.y);
                float w1 = __int_as_float(e1.y);
                uint2 u0 = Hu[(size_t)e0.x * 32 + lane];
                uint2 u1 = Hu[(size_t)e1.x * 32 + lane];
                float2 a0 = h2f(u0.x), b0 = h2f(u0.y);
                float2 a1 = h2f(u1.x), b1 = h2f(u1.y);
                acc.x += w0 * a0.x + w1 * a1.x;
                acc.y += w0 * a0.y + w1 * a1.y;
                acc.z += w0 * b0.x + w1 * b1.x;
                acc.w += w0 * b0.y + w1 * b1.y;
            }
            if (k < cnt) {
                int2 e0 = g_edge[beg + k];
                float w0 = __int_as_float(e0.y);
                uint2 u0 = Hu[(size_t)e0.x * 32 + lane];
                float2 a0 = h2f(u0.x), b0 = h2f(u0.y);
                acc.x += w0 * a0.x;
                acc.y += w0 * a0.y;
                acc.z += w0 * b0.x;
                acc.w += w0 * b0.y;
            }
            row[lane * 4]     = acc.x;
            row[lane * 4 + 1] = acc.y;
            row[lane * 4 + 2] = acc.z;
            row[lane * 4 + 3] = acc.w;
        } else {
            row[lane * 4]     = 0.0f;
            row[lane * 4 + 1] = 0.0f;
            row[lane * 4 + 2] = 0.0f;
            row[lane * 4 + 3] = 0.0f;
        }
    }
    __syncthreads();

    // phase 2: GEMM (64x128) x (128x128), W tiled 32 rows at a time
    const int tx = tid & 15;
    const int ty = tid >> 4;
    unsigned long long acc[4][4];
#pragma unroll
    for (int i = 0; i < 4; ++i)
#pragma unroll
        for (int jj = 0; jj < 4; ++jj) acc[i][jj] = 0ull;

    float bv[8];
#pragma unroll
    for (int jj = 0; jj < 8; ++jj) bv[jj] = __ldg(&bias[tx * 8 + jj]);

    for (int k0 = 0; k0 < C_HID; k0 += 32) {
#pragma unroll
        for (int it = 0; it < 16; ++it) {
            int i = tid + it * 256;
            int kk = i >> 7, cc = i & 127;
            Ws[kk * 128 + cc] = W[(size_t)(k0 + kk) * C_HID + cc];
        }
        __syncthreads();
#pragma unroll 8
        for (int kk = 0; kk < 32; ++kk) {
            float4 bA = *(const float4*)&Ws[kk * 128 + tx * 8];
            float4 bB = *(const float4*)&Ws[kk * 128 + tx * 8 + 4];
            unsigned long long bp0 = pack2(bA.x, bA.y);
            unsigned long long bp1 = pack2(bA.z, bA.w);
            unsigned long long bp2 = pack2(bB.x, bB.y);
            unsigned long long bp3 = pack2(bB.z, bB.w);
#pragma unroll
            for (int i = 0; i < 4; ++i) {
                float av = As[(ty * 4 + i) * 129 + k0 + kk];
                unsigned long long a2 = pack2(av, av);
                acc[i][0] = fma2(a2, bp0, acc[i][0]);
                acc[i][1] = fma2(a2, bp1, acc[i][1]);
                acc[i][2] = fma2(a2, bp2, acc[i][2]);
                acc[i][3] = fma2(a2, bp3, acc[i][3]);
            }
        }
        __syncthreads();
    }

    // phase 3: relu -> smem, then per-column pooled reduction
#pragma unroll
    for (int i = 0; i < 4; ++i) {
        int r = ty * 4 + i;
        float2 r0 = unpack2(acc[i][0]);
        float2 r1 = unpack2(acc[i][1]);
        float2 r2 = unpack2(acc[i][2]);
        float2 r3 = unpack2(acc[i][3]);
        float* rp = &As[r * 129 + tx * 8];
        rp[0] = fmaxf(r0.x + bv[0], 0.0f);
        rp[1] = fmaxf(r0.y + bv[1], 0.0f);
        rp[2] = fmaxf(r1.x + bv[2], 0.0f);
        rp[3] = fmaxf(r1.y + bv[3], 0.0f);
        rp[4] = fmaxf(r2.x + bv[4], 0.0f);
        rp[5] = fmaxf(r2.y + bv[5], 0.0f);
        rp[6] = fmaxf(r3.x + bv[6], 0.0f);
        rp[7] = fmaxf(r3.y + bv[7], 0.0f);
    }
    __syncthreads();

    if (tid < 128 && lim > 0) {
        int c = tid;
        float accp = 0.0f;
        int g = sbat[0];
        for (int r = 0; r < lim; ++r) {
            int gb = sbat[r];
            if (gb != g) {
                atomicAdd(&g_pooled[g * C_HID + c], accp);
                g = gb; accp = 0.0f;
            }
            accp += As[r * 129 + c];
        }
        atomicAdd(&g_pooled[g * C_HID + c], accp);
    }
}

// ---------------- graph-size histogram ----------------
__global__ __launch_bounds__(256) void k_cnt(const void* __restrict__ batch) {
    __shared__ int h[NG];
    if (threadIdx.x < NG) h[threadIdx.x] = 0;
    __syncthreads();
    int n = blockIdx.x * 256 + threadIdx.x;
    if (n < NN) {
        int g = read_idx(batch, n);
        g = min(max(g, 0), NG - 1);
        atomicAdd(&h[g], 1);
    }
    __syncthreads();
    if (threadIdx.x < NG && h[threadIdx.x] > 0)
        atomicAdd(&g_cnt[threadIdx.x], (float)h[threadIdx.x]);
}

// ---------------- classifier head ----------------
__global__ void k_final(const float* __restrict__ Wc, const float* __restrict__ bc,
                        float* __restrict__ out) {
    int t = threadIdx.x;
    if (t >= NG * NC) return;
    int g = t / NC, c = t % NC;
    float inv = 1.0f / fmaxf(g_cnt[g], 1.0f);
    float s = 0.0f;
#pragma unroll 16
    for (int h = 0; h < C_HID; ++h)
        s += g_pooled[g * C_HID + h] * __ldg(&Wc[h * NC + c]);
    out[t] = s * inv + bc[c];
}

// ---------------- launch ----------------
extern "C" void kernel_launch(void* const* d_in, const int* in_sizes, int n_in,
                              void* d_out, int out_size) {
    const float* x = 0; const float* W1 = 0; const float* b1 = 0;
    const float* W2 = 0; const float* b2 = 0; const float* Wc = 0;
    const float* bc = 0; const void* ei = 0; const void* batch = 0;
    for (int i = 0; i < n_in; ++i) {
        int s = in_sizes[i];
        void* p = d_in[i];
        if      (s == NN * C_IN)     x  = (const float*)p;
        else if (s == C_IN * C_HID)  W1 = (const float*)p;
        else if (s == C_HID * C_HID) W2 = (const float*)p;
        else if (s == C_HID * NC)    Wc = (const float*)p;
        else if (s == NC)            bc = (const float*)p;
        else if (s == 2 * NE)        ei = p;
        else if (s == NN)            batch = p;
        else if (s == C_HID)         { if (!b1) b1 = (const float*)p; else b2 = (const float*)p; }
    }
    if (!b2) b2 = b1;
    float* out = (float*)d_out;
    (void)out_size;

    static int attr_done = 0;
    if (!attr_done) {
        cudaFuncSetAttribute(k_fused2, cudaFuncAttributeMaxDynamicSharedMemorySize, F2_SMEM);
        attr_done = 1;
    }

    const int T = 256;

    k_detect<<<1, 32>>>(ei);                              // 0
    k_init<<<NBLK, T>>>();                                // 1
    k_tohalf<<<(NN * C_IN / 4 + T - 1) / T, T>>>(x);      // 2
    k_edge_prep<<<(NE + T - 1) / T, T>>>(ei);             // 3
    k_blocksum<<<NBLK, T>>>();                            // 4
    k_bscan<<<1, 512>>>();                                // 5
    k_offsets<<<NBLK, T>>>();                             // 6
    k_csr_fill<<<(NE + T - 1) / T, T>>>(ei);              // 7
    k_cnt<<<NBLK, T>>>(batch);                            // 8

    k_fused1<<<NTILE, T>>>(W1, b1);                       // 9
    k_fused2<<<NTILE, T, F2_SMEM>>>(W2, b2, batch);       // 10

    k_final<<<1, 640>>>(Wc, bc, out);                     // 11
}

// round 8
// speedup vs baseline: 1.9769x; 1.0113x over previous
#include <cuda_runtime.h>
#include <cuda_fp16.h>

#define NN 100000
#define NE 1600000
#define C_IN 64
#define C_HID 128
#define NG 64
#define NC 10
#define NBLK ((NN + 255) / 256)   // 391
#define NTILE ((NN + 63) / 64)    // 1563

// ---------------- scratch (__device__ globals; no allocations) ----------------
static __device__ __align__(16) int    g_degi[NN];
static __device__ __align__(16) int    g_off[NN];
static __device__ __align__(16) int    g_cur[NN];
static __device__ __align__(16) float  g_dinv[NN];
static __device__ __align__(16) int    g_bsum[NBLK];
static __device__ __align__(16) int    g_boff[NBLK];
static __device__ __align__(16) int2   g_edge[NE];     // CSR payload: {src, norm-bits}
static __device__ __align__(16) __half g_xh[(size_t)NN * C_IN];    // 12.8 MB
static __device__ __align__(16) __half g_h1h[(size_t)NN * C_HID];  // 25.6 MB
static __device__ __align__(16) float  g_pooled[NG * C_HID];
static __device__ __align__(16) float  g_cnt[NG];
static __device__ int g_is64;

__device__ __forceinline__ int read_idx(const void* p, long long i) {
    if (g_is64) return (int)((const long long*)p)[i];
    return ((const int*)p)[i];
}

// ---------------- packed fp32x2 helpers (Blackwell FFMA2) ----------------
__device__ __forceinline__ unsigned long long pack2(float lo, float hi) {
    unsigned long long r;
    asm("mov.b64 %0, {%1, %2};" : "=l"(r) : "f"(lo), "f"(hi));
    return r;
}
__device__ __forceinline__ float2 unpack2(unsigned long long v) {
    float2 f;
    asm("mov.b64 {%0, %1}, %2;" : "=f"(f.x), "=f"(f.y) : "l"(v));
    return f;
}
__device__ __forceinline__ unsigned long long fma2(unsigned long long a,
                                                   unsigned long long b,
                                                   unsigned long long c) {
    unsigned long long d;
    asm("fma.rn.f32x2 %0, %1, %2, %3;" : "=l"(d) : "l"(a), "l"(b), "l"(c));
    return d;
}
__device__ __forceinline__ float2 h2f(unsigned u) {
    __half2 h = *(__half2*)&u;
    return __half22float2(h);
}

// ---------------- dtype detection ----------------
__global__ void k_detect(const void* __restrict__ ei) {
    if (threadIdx.x == 0) {
        const long long* p = (const long long*)ei;
        int ok64 = 1;
        for (int i = 0; i < 64; ++i) {
            long long v = p[i];
            if (v < 0 || v >= NN) { ok64 = 0; break; }
        }
        g_is64 = ok64;
    }
}

// ---------------- prep ----------------
__global__ void k_init() {
    int t = blockIdx.x * blockDim.x + threadIdx.x;
    if (t < NN) g_degi[t] = 0;
    if (t < NG * C_HID) g_pooled[t] = 0.0f;
    if (t < NG) g_cnt[t] = 0.0f;
}

// x -> fp16 (4 floats per thread)
__global__ __launch_bounds__(256) void k_tohalf(const float* __restrict__ X) {
    int i = blockIdx.x * blockDim.x + threadIdx.x;
    const int total = NN * C_IN / 4;
    if (i >= total) return;
    float4 v = ((const float4*)X)[i];
    __half2 a = __floats2half2_rn(v.x, v.y);
    __half2 b = __floats2half2_rn(v.z, v.w);
    uint2 u;
    u.x = *(unsigned*)&a;
    u.y = *(unsigned*)&b;
    ((uint2*)g_xh)[i] = u;
}

__global__ void k_edge_prep(const void* __restrict__ ei) {
    int e = blockIdx.x * blockDim.x + threadIdx.x;
    if (e >= NE) return;
    int d = read_idx(ei, (long long)NE + e);
    d = min(max(d, 0), NN - 1);
    atomicAdd(&g_degi[d], 1);
}

// ---- parallel 3-phase exclusive scan over g_degi ----
__global__ __launch_bounds__(256) void k_blocksum() {
    __shared__ int ws[8];
    int i = blockIdx.x * 256 + threadIdx.x;
    int v = (i < NN) ? g_degi[i] : 0;
    int lane = threadIdx.x & 31, wid = threadIdx.x >> 5;
#pragma unroll
    for (int o = 16; o > 0; o >>= 1) v += __shfl_down_sync(0xFFFFFFFFu, v, o);
    if (lane == 0) ws[wid] = v;
    __syncthreads();
    if (threadIdx.x == 0) {
        int s = 0;
#pragma unroll
        for (int w = 0; w < 8; ++w) s += ws[w];
        g_bsum[blockIdx.x] = s;
    }
}

__global__ __launch_bounds__(512) void k_bscan() {
    __shared__ int sh[512];
    int t = threadIdx.x;
    sh[t] = (t < NBLK) ? g_bsum[t] : 0;
    __syncthreads();
#pragma unroll
    for (int o = 1; o < 512; o <<= 1) {
        int v = (t >= o) ? sh[t - o] : 0;
        __syncthreads();
        sh[t] += v;
        __syncthreads();
    }
    if (t < NBLK) g_boff[t] = sh[t] - g_bsum[t];   // exclusive
}

__global__ __launch_bounds__(256) void k_offsets() {
    __shared__ int ws[8];
    int i = blockIdx.x * 256 + threadIdx.x;
    int deg = (i < NN) ? g_degi[i] : 0;
    int lane = threadIdx.x & 31, wid = threadIdx.x >> 5;
    int v = deg;
#pragma unroll
    for (int o = 1; o < 32; o <<= 1) {
        int t = __shfl_up_sync(0xFFFFFFFFu, v, o);
        if (lane >= o) v += t;
    }
    if (lane == 31) ws[wid] = v;
    __syncthreads();
    if (wid == 0 && lane < 8) {
        int w = ws[lane];
#pragma unroll
        for (int o = 1; o < 8; o <<= 1) {
            int t = __shfl_up_sync(0xFFu, w, o);
            if (lane >= o) w += t;
        }
        ws[lane] = w;
    }
    __syncthreads();
    int excl = v - deg + (wid > 0 ? ws[wid - 1] : 0) + g_boff[blockIdx.x];
    if (i < NN) {
        g_off[i] = excl;
        g_cur[i] = excl;
        g_dinv[i] = rsqrtf((float)(deg + 1));
    }
}

// fill CSR payload {src, norm} bucketed by dst
__global__ void k_csr_fill(const void* __restrict__ ei) {
    int e = blockIdx.x * blockDim.x + threadIdx.x;
    if (e >= NE) return;
    int s = read_idx(ei, e);
    int d = read_idx(ei, (long long)NE + e);
    s = min(max(s, 0), NN - 1);
    d = min(max(d, 0), NN - 1);
    int pos = atomicAdd(&g_cur[d], 1);
    float nrm = g_dinv[s] * g_dinv[d];
    g_edge[pos] = make_int2(s, __float_as_int(nrm));
}

// ---------------- fused layer 1: gather-agg(x_h,64) + GEMM W1 + bias + relu -> H1(fp16) ----------------
__global__ __launch_bounds__(256)
void k_fused1(const float* __restrict__ W, const float* __restrict__ bias) {
    __shared__ float As[64][65];
    __shared__ float Ws[32][128];

    const int tid = threadIdx.x;
    const int lane = tid & 31;
    const int w = tid >> 5;
    const int node_base = blockIdx.x * 64;
    const unsigned* __restrict__ Xu = (const unsigned*)g_xh;   // half2 words; row = node*32
    const int2* __restrict__ E = g_edge;

    // phase 1: warp-per-node gather aggregation, unroll 4 for MLP
    for (int j = w; j < 64; j += 8) {
        int node = node_base + j;
        if (node < NN) {
            float di = g_dinv[node];
            float sw = di * di;
            float2 acc = h2f(Xu[node * 32 + lane]);
            acc.x *= sw; acc.y *= sw;
            int beg = g_off[node];
            int cnt = g_degi[node];
            int k = 0;
            for (; k + 4 <= cnt; k += 4) {
                int2 e0 = E[beg + k];
                int2 e1 = E[beg + k + 1];
                int2 e2 = E[beg + k + 2];
                int2 e3 = E[beg + k + 3];
                float2 v0 = h2f(Xu[e0.x * 32 + lane]);
                float2 v1 = h2f(Xu[e1.x * 32 + lane]);
                float2 v2 = h2f(Xu[e2.x * 32 + lane]);
                float2 v3 = h2f(Xu[e3.x * 32 + lane]);
                float w0 = __int_as_float(e0.y);
                float w1 = __int_as_float(e1.y);
                float w2 = __int_as_float(e2.y);
                float w3 = __int_as_float(e3.y);
                acc.x += w0 * v0.x + w1 * v1.x + w2 * v2.x + w3 * v3.x;
                acc.y += w0 * v0.y + w1 * v1.y + w2 * v2.y + w3 * v3.y;
            }
            for (; k < cnt; ++k) {
                int2 e0 = E[beg + k];
                float w0 = __int_as_float(e0.y);
                float2 v0 = h2f(Xu[e0.x * 32 + lane]);
                acc.x += w0 * v0.x;
                acc.y += w0 * v0.y;
            }
            As[j][lane * 2] = acc.x;
            As[j][lane * 2 + 1] = acc.y;
        } else {
            As[j][lane * 2] = 0.0f;
            As[j][lane * 2 + 1] = 0.0f;
        }
    }
    __syncthreads();

    // phase 2: GEMM (64x64) x (64x128)
    const int tx = tid & 15;
    const int ty = tid >> 4;
    unsigned long long acc[4][4];
#pragma unroll
    for (int i = 0; i < 4; ++i)
#pragma unroll
        for (int jj = 0; jj < 4; ++jj) acc[i][jj] = 0ull;

    float bv[8];
#pragma unroll
    for (int jj = 0; jj < 8; ++jj) bv[jj] = __ldg(&bias[tx * 8 + jj]);

#pragma unroll
    for (int k0 = 0; k0 < 64; k0 += 32) {
#pragma unroll
        for (int it = 0; it < 16; ++it) {
            int i = tid + it * 256;
            int kk = i >> 7, cc = i & 127;
            Ws[kk][cc] = W[(size_t)(k0 + kk) * C_HID + cc];
        }
        __syncthreads();
#pragma unroll 8
        for (int kk = 0; kk < 32; ++kk) {
            float4 bA = *(const float4*)&Ws[kk][tx * 8];
            float4 bB = *(const float4*)&Ws[kk][tx * 8 + 4];
            unsigned long long bp0 = pack2(bA.x, bA.y);
            unsigned long long bp1 = pack2(bA.z, bA.w);
            unsigned long long bp2 = pack2(bB.x, bB.y);
            unsigned long long bp3 = pack2(bB.z, bB.w);
#pragma unroll
            for (int i = 0; i < 4; ++i) {
                float av = As[ty * 4 + i][k0 + kk];
                unsigned long long a2 = pack2(av, av);
                acc[i][0] = fma2(a2, bp0, acc[i][0]);
                acc[i][1] = fma2(a2, bp1, acc[i][1]);
                acc[i][2] = fma2(a2, bp2, acc[i][2]);
                acc[i][3] = fma2(a2, bp3, acc[i][3]);
            }
        }
        __syncthreads();
    }

    // epilogue: bias + relu -> fp16 store
#pragma unroll
    for (int i = 0; i < 4; ++i) {
        int grow = node_base + ty * 4 + i;
        if (grow < NN) {
            float2 r0 = unpack2(acc[i][0]);
            float2 r1 = unpack2(acc[i][1]);
            float2 r2 = unpack2(acc[i][2]);
            float2 r3 = unpack2(acc[i][3]);
            __half2 h0 = __floats2half2_rn(fmaxf(r0.x + bv[0], 0.0f), fmaxf(r0.y + bv[1], 0.0f));
            __half2 h1 = __floats2half2_rn(fmaxf(r1.x + bv[2], 0.0f), fmaxf(r1.y + bv[3], 0.0f));
            __half2 h2 = __floats2half2_rn(fmaxf(r2.x + bv[4], 0.0f), fmaxf(r2.y + bv[5], 0.0f));
            __half2 h3 = __floats2half2_rn(fmaxf(r3.x + bv[6], 0.0f), fmaxf(r3.y + bv[7], 0.0f));
            uint4 u;
            u.x = *(unsigned*)&h0;
            u.y = *(unsigned*)&h1;
            u.z = *(unsigned*)&h2;
            u.w = *(unsigned*)&h3;
            ((uint4*)g_h1h)[(size_t)grow * 16 + tx] = u;
        }
    }
}

// ---------------- fused layer 2: gather-agg(H1h,128) + GEMM W2(tiled) + relu + mean-pool ----------------
#define F2_AS   (64 * 129)
#define F2_WS   (32 * 128)
#define F2_SMEM ((F2_AS + F2_WS) * 4 + 64 * 4)

__global__ __launch_bounds__(256)
void k_fused2(const float* __restrict__ W, const float* __restrict__ bias,
              const void* __restrict__ batch) {
    extern __shared__ float sm[];
    float* As = sm;                    // [64][129]
    float* Ws = sm + F2_AS;            // [32][128]
    int*   sbat = (int*)(Ws + F2_WS);  // [64]

    const int tid = threadIdx.x;
    const int lane = tid & 31;
    const int w = tid >> 5;
    const int node_base = blockIdx.x * 64;
    const int lim = min(64, NN - node_base);
    const uint2* __restrict__ Hu = (const uint2*)g_h1h;   // 4 halves; row = node*32
    const int2* __restrict__ E = g_edge;

    if (tid < 64) {
        int n = node_base + tid;
        int g = 0;
        if (n < NN) g = read_idx(batch, n);
        sbat[tid] = min(max(g, 0), NG - 1);
    }

    // phase 1: warp-per-node gather aggregation, unroll 4 for MLP
    for (int j = w; j < 64; j += 8) {
        int node = node_base + j;
        float* row = &As[j * 129];
        if (node < NN) {
            float di = g_dinv[node];
            float sw = di * di;
            uint2 su = Hu[(size_t)node * 32 + lane];
            float2 sa = h2f(su.x), sb = h2f(su.y);
            float4 acc = make_float4(sa.x * sw, sa.y * sw, sb.x * sw, sb.y * sw);
            int beg = g_off[node];
            int cnt = g_degi[node];
            int k = 0;
            for (; k + 4 <= cnt; k += 4) {
                int2 e0 = E[beg + k];
                int2 e1 = E[beg + k + 1];
                int2 e2 = E[beg + k + 2];
                int2 e3 = E[beg + k + 3];
                uint2 u0 = Hu[(size_t)e0.x * 32 + lane];
                uint2 u1 = Hu[(size_t)e1.x * 32 + lane];
                uint2 u2 = Hu[(size_t)e2.x * 32 + lane];
                uint2 u3 = Hu[(size_t)e3.x * 32 + lane];
                float w0 = __int_as_float(e0.y);
                float w1 = __int_as_float(e1.y);
                float w2 = __int_as_float(e2.y);
                float w3 = __int_as_float(e3.y);
                float2 a0 = h2f(u0.x), b0 = h2f(u0.y);
                float2 a1 = h2f(u1.x), b1 = h2f(u1.y);
                float2 a2 = h2f(u2.x), b2 = h2f(u2.y);
                float2 a3 = h2f(u3.x), b3 = h2f(u3.y);
                acc.x += w0 * a0.x + w1 * a1.x + w2 * a2.x + w3 * a3.x;
                acc.y += w0 * a0.y + w1 * a1.y + w2 * a2.y + w3 * a3.y;
                acc.z += w0 * b0.x + w1 * b1.x + w2 * b2.x + w3 * b3.x;
                acc.w += w0 * b0.y + w1 * b1.y + w2 * b2.y + w3 * b3.y;
            }
            for (; k < cnt; ++k) {
                int2 e0 = E[beg + k];
                float w0 = __int_as_float(e0.y);
                uint2 u0 = Hu[(size_t)e0.x * 32 + lane];
                float2 a0 = h2f(u0.x), b0 = h2f(u0.y);
                acc.x += w0 * a0.x;
                acc.y += w0 * a0.y;
                acc.z += w0 * b0.x;
                acc.w += w0 * b0.y;
            }
            row[lane * 4]     = acc.x;
            row[lane * 4 + 1] = acc.y;
            row[lane * 4 + 2] = acc.z;
            row[lane * 4 + 3] = acc.w;
        } else {
            row[lane * 4]     = 0.0f;
            row[lane * 4 + 1] = 0.0f;
            row[lane * 4 + 2] = 0.0f;
            row[lane * 4 + 3] = 0.0f;
        }
    }
    __syncthreads();

    // phase 2: GEMM (64x128) x (128x128), W tiled 32 rows at a time
    const int tx = tid & 15;
    const int ty = tid >> 4;
    unsigned long long acc[4][4];
#pragma unroll
    for (int i = 0; i < 4; ++i)
#pragma unroll
        for (int jj = 0; jj < 4; ++jj) acc[i][jj] = 0ull;

    float bv[8];
#pragma unroll
    for (int jj = 0; jj < 8; ++jj) bv[jj] = __ldg(&bias[tx * 8 + jj]);

    for (int k0 = 0; k0 < C_HID; k0 += 32) {
#pragma unroll
        for (int it = 0; it < 16; ++it) {
            int i = tid + it * 256;
            int kk = i >> 7, cc = i & 127;
            Ws[kk * 128 + cc] = W[(size_t)(k0 + kk) * C_HID + cc];
        }
        __syncthreads();
#pragma unroll 8
        for (int kk = 0; kk < 32; ++kk) {
            float4 bA = *(const float4*)&Ws[kk * 128 + tx * 8];
            float4 bB = *(const float4*)&Ws[kk * 128 + tx * 8 + 4];
            unsigned long long bp0 = pack2(bA.x, bA.y);
            unsigned long long bp1 = pack2(bA.z, bA.w);
            unsigned long long bp2 = pack2(bB.x, bB.y);
            unsigned long long bp3 = pack2(bB.z, bB.w);
#pragma unroll
            for (int i = 0; i < 4; ++i) {
                float av = As[(ty * 4 + i) * 129 + k0 + kk];
                unsigned long long a2 = pack2(av, av);
                acc[i][0] = fma2(a2, bp0, acc[i][0]);
                acc[i][1] = fma2(a2, bp1, acc[i][1]);
                acc[i][2] = fma2(a2, bp2, acc[i][2]);
                acc[i][3] = fma2(a2, bp3, acc[i][3]);
            }
        }
        __syncthreads();
    }

    // phase 3: relu -> smem, then per-column pooled reduction
#pragma unroll
    for (int i = 0; i < 4; ++i) {
        int r = ty * 4 + i;
        float2 r0 = unpack2(acc[i][0]);
        float2 r1 = unpack2(acc[i][1]);
        float2 r2 = unpack2(acc[i][2]);
        float2 r3 = unpack2(acc[i][3]);
        float* rp = &As[r * 129 + tx * 8];
        rp[0] = fmaxf(r0.x + bv[0], 0.0f);
        rp[1] = fmaxf(r0.y + bv[1], 0.0f);
        rp[2] = fmaxf(r1.x + bv[2], 0.0f);
        rp[3] = fmaxf(r1.y + bv[3], 0.0f);
        rp[4] = fmaxf(r2.x + bv[4], 0.0f);
        rp[5] = fmaxf(r2.y + bv[5], 0.0f);
        rp[6] = fmaxf(r3.x + bv[6], 0.0f);
        rp[7] = fmaxf(r3.y + bv[7], 0.0f);
    }
    __syncthreads();

    if (tid < 128 && lim > 0) {
        int c = tid;
        float accp = 0.0f;
        int g = sbat[0];
        for (int r = 0; r < lim; ++r) {
            int gb = sbat[r];
            if (gb != g) {
                atomicAdd(&g_pooled[g * C_HID + c], accp);
                g = gb; accp = 0.0f;
            }
            accp += As[r * 129 + c];
        }
        atomicAdd(&g_pooled[g * C_HID + c], accp);
    }
}

// ---------------- graph-size histogram ----------------
__global__ __launch_bounds__(256) void k_cnt(const void* __restrict__ batch) {
    __shared__ int h[NG];
    if (threadIdx.x < NG) h[threadIdx.x] = 0;
    __syncthreads();
    int n = blockIdx.x * 256 + threadIdx.x;
    if (n < NN) {
        int g = read_idx(batch, n);
        g = min(max(g, 0), NG - 1);
        atomicAdd(&h[g], 1);
    }
    __syncthreads();
    if (threadIdx.x < NG && h[threadIdx.x] > 0)
        atomicAdd(&g_cnt[threadIdx.x], (float)h[threadIdx.x]);
}

// ---------------- classifier head ----------------
__global__ void k_final(const float* __restrict__ Wc, const float* __restrict__ bc,
                        float* __restrict__ out) {
    int t = threadIdx.x;
    if (t >= NG * NC) return;
    int g = t / NC, c = t % NC;
    float inv = 1.0f / fmaxf(g_cnt[g], 1.0f);
    float s = 0.0f;
#pragma unroll 16
    for (int h = 0; h < C_HID; ++h)
        s += g_pooled[g * C_HID + h] * __ldg(&Wc[h * NC + c]);
    out[t] = s * inv + bc[c];
}

// ---------------- launch ----------------
extern "C" void kernel_launch(void* const* d_in, const int* in_sizes, int n_in,
                              void* d_out, int out_size) {
    const float* x = 0; const float* W1 = 0; const float* b1 = 0;
    const float* W2 = 0; const float* b2 = 0; const float* Wc = 0;
    const float* bc = 0; const void* ei = 0; const void* batch = 0;
    for (int i = 0; i < n_in; ++i) {
        int s = in_sizes[i];
        void* p = d_in[i];
        if      (s == NN * C_IN)     x  = (const float*)p;
        else if (s == C_IN * C_HID)  W1 = (const float*)p;
        else if (s == C_HID * C_HID) W2 = (const float*)p;
        else if (s == C_HID * NC)    Wc = (const float*)p;
        else if (s == NC)            bc = (const float*)p;
        else if (s == 2 * NE)        ei = p;
        else if (s == NN)            batch = p;
        else if (s == C_HID)         { if (!b1) b1 = (const float*)p; else b2 = (const float*)p; }
    }
    if (!b2) b2 = b1;
    float* out = (float*)d_out;
    (void)out_size;

    static int attr_done = 0;
    if (!attr_done) {
        cudaFuncSetAttribute(k_fused2, cudaFuncAttributeMaxDynamicSharedMemorySize, F2_SMEM);
        attr_done = 1;
    }

    const int T = 256;

    k_detect<<<1, 32>>>(ei);                              // 0
    k_init<<<NBLK, T>>>();                                // 1
    k_tohalf<<<(NN * C_IN / 4 + T - 1) / T, T>>>(x);      // 2
    k_edge_prep<<<(NE + T - 1) / T, T>>>(ei);             // 3
    k_blocksum<<<NBLK, T>>>();                            // 4
    k_bscan<<<1, 512>>>();                                // 5
    k_offsets<<<NBLK, T>>>();                             // 6
    k_csr_fill<<<(NE + T - 1) / T, T>>>(ei);              // 7
    k_cnt<<<NBLK, T>>>(batch);                            // 8

    k_fused1<<<NTILE, T>>>(W1, b1);                       // 9
    k_fused2<<<NTILE, T, F2_SMEM>>>(W2, b2, batch);       // 10

    k_final<<<1, 640>>>(Wc, bc, out);                     // 11
}

// round 9
// speedup vs baseline: 3.3591x; 1.6992x over previous
#include <cuda_runtime.h>
#include <cuda_fp16.h>

#define NN 100000
#define NE 1600000
#define C_IN 64
#define C_HID 128
#define NG 64
#define NC 10
#define NBLK ((NN + 255) / 256)   // 391
#define NTILE ((NN + 63) / 64)    // 1563

// ---------------- scratch (__device__ globals; no allocations) ----------------
static __device__ __align__(16) int    g_degi[NN];
static __device__ __align__(16) int    g_off[NN];
static __device__ __align__(16) int    g_cur[NN];
static __device__ __align__(16) float  g_dinv[NN];
static __device__ __align__(16) int    g_bsum[NBLK];
static __device__ __align__(16) int    g_boff[NBLK];
static __device__ __align__(16) int2   g_edge[NE];     // CSR payload: {src, norm-bits}
static __device__ __align__(16) __half g_xh[(size_t)NN * C_IN];    // 12.8 MB
static __device__ __align__(16) __half g_h1h[(size_t)NN * C_HID];  // 25.6 MB
static __device__ __align__(16) __half g_w1h[C_IN * C_HID];
static __device__ __align__(16) __half g_w2h[C_HID * C_HID];
static __device__ __align__(16) float  g_pooled[NG * C_HID];
static __device__ __align__(16) float  g_cnt[NG];
static __device__ int g_is64;

__device__ __forceinline__ int read_idx(const void* p, long long i) {
    if (g_is64) return (int)((const long long*)p)[i];
    return ((const int*)p)[i];
}
__device__ __forceinline__ float2 h2f(unsigned u) {
    __half2 h = *(__half2*)&u;
    return __half22float2(h);
}
__device__ __forceinline__ unsigned s2u(const void* p) {
    return (unsigned)__cvta_generic_to_shared(p);
}

// ---------------- mma / ldmatrix helpers ----------------
__device__ __forceinline__ void mma_f16(float c[4], unsigned a0, unsigned a1,
                                        unsigned a2, unsigned a3,
                                        unsigned b0, unsigned b1) {
    asm volatile(
        "mma.sync.aligned.m16n8k16.row.col.f32.f16.f16.f32 "
        "{%0,%1,%2,%3}, {%4,%5,%6,%7}, {%8,%9}, {%0,%1,%2,%3};"
        : "+f"(c[0]), "+f"(c[1]), "+f"(c[2]), "+f"(c[3])
        : "r"(a0), "r"(a1), "r"(a2), "r"(a3), "r"(b0), "r"(b1));
}
__device__ __forceinline__ void ldsm_x4(unsigned& r0, unsigned& r1, unsigned& r2,
                                        unsigned& r3, unsigned addr) {
    asm volatile("ldmatrix.sync.aligned.m8n8.x4.shared.b16 {%0,%1,%2,%3}, [%4];"
                 : "=r"(r0), "=r"(r1), "=r"(r2), "=r"(r3) : "r"(addr));
}
__device__ __forceinline__ void ldsm_x4_t(unsigned& r0, unsigned& r1, unsigned& r2,
                                          unsigned& r3, unsigned addr) {
    asm volatile("ldmatrix.sync.aligned.m8n8.x4.trans.shared.b16 {%0,%1,%2,%3}, [%4];"
                 : "=r"(r0), "=r"(r1), "=r"(r2), "=r"(r3) : "r"(addr));
}

// GEMM phase: acc[8][4] += As[mt*16..+16, 0..K) x W[0..K, nh*64..+64)
// As: fp16 smem, row stride LDA halves; W: fp16 smem, row stride 136 halves.
template<int K, int LDA>
__device__ __forceinline__ void mma_gemm_phase(unsigned asb, unsigned wb, int lane,
                                               int mt, int nh, float acc[8][4]) {
    const int m0 = mt * 16;
    unsigned a_base = asb + (((m0 + (lane & 15)) * LDA) + ((lane >> 4) << 3)) * 2;
    const int brow = (lane & 7) + (lane & 8);
    const int bcol = nh * 64 + ((lane & 16) >> 1);
#pragma unroll
    for (int k0 = 0; k0 < K; k0 += 16) {
        unsigned a0, a1, a2, a3;
        ldsm_x4(a0, a1, a2, a3, a_base + k0 * 2);
#pragma unroll
        for (int p = 0; p < 4; ++p) {
            unsigned b0, b1, b2, b3;
            unsigned baddr = wb + (((k0 + brow) * 136) + bcol + p * 16) * 2;
            ldsm_x4_t(b0, b1, b2, b3, baddr);
            mma_f16(acc[2 * p],     a0, a1, a2, a3, b0, b1);
            mma_f16(acc[2 * p + 1], a0, a1, a2, a3, b2, b3);
        }
    }
}

// ---------------- dtype detection ----------------
__global__ void k_detect(const void* __restrict__ ei) {
    if (threadIdx.x == 0) {
        const long long* p = (const long long*)ei;
        int ok64 = 1;
        for (int i = 0; i < 64; ++i) {
            long long v = p[i];
            if (v < 0 || v >= NN) { ok64 = 0; break; }
        }
        g_is64 = ok64;
    }
}

// ---------------- prep ----------------
__global__ void k_init() {
    int t = blockIdx.x * blockDim.x + threadIdx.x;
    if (t < NN) g_degi[t] = 0;
    if (t < NG * C_HID) g_pooled[t] = 0.0f;
    if (t < NG) g_cnt[t] = 0.0f;
}

__global__ __launch_bounds__(256) void k_tohalf(const float* __restrict__ X) {
    int i = blockIdx.x * blockDim.x + threadIdx.x;
    const int total = NN * C_IN / 4;
    if (i >= total) return;
    float4 v = ((const float4*)X)[i];
    __half2 a = __floats2half2_rn(v.x, v.y);
    __half2 b = __floats2half2_rn(v.z, v.w);
    uint2 u;
    u.x = *(unsigned*)&a;
    u.y = *(unsigned*)&b;
    ((uint2*)g_xh)[i] = u;
}

__global__ __launch_bounds__(256) void k_whalf(const float* __restrict__ W,
                                               __half* __restrict__ dst, int n2) {
    int i = blockIdx.x * blockDim.x + threadIdx.x;
    if (i >= n2) return;
    float2 v = ((const float2*)W)[i];
    ((__half2*)dst)[i] = __floats2half2_rn(v.x, v.y);
}

__global__ void k_edge_prep(const void* __restrict__ ei) {
    int e = blockIdx.x * blockDim.x + threadIdx.x;
    if (e >= NE) return;
    int d = read_idx(ei, (long long)NE + e);
    d = min(max(d, 0), NN - 1);
    atomicAdd(&g_degi[d], 1);
}

// ---- parallel 3-phase exclusive scan over g_degi ----
__global__ __launch_bounds__(256) void k_blocksum() {
    __shared__ int ws[8];
    int i = blockIdx.x * 256 + threadIdx.x;
    int v = (i < NN) ? g_degi[i] : 0;
    int lane = threadIdx.x & 31, wid = threadIdx.x >> 5;
#pragma unroll
    for (int o = 16; o > 0; o >>= 1) v += __shfl_down_sync(0xFFFFFFFFu, v, o);
    if (lane == 0) ws[wid] = v;
    __syncthreads();
    if (threadIdx.x == 0) {
        int s = 0;
#pragma unroll
        for (int w = 0; w < 8; ++w) s += ws[w];
        g_bsum[blockIdx.x] = s;
    }
}

__global__ __launch_bounds__(512) void k_bscan() {
    __shared__ int sh[512];
    int t = threadIdx.x;
    sh[t] = (t < NBLK) ? g_bsum[t] : 0;
    __syncthreads();
#pragma unroll
    for (int o = 1; o < 512; o <<= 1) {
        int v = (t >= o) ? sh[t - o] : 0;
        __syncthreads();
        sh[t] += v;
        __syncthreads();
    }
    if (t < NBLK) g_boff[t] = sh[t] - g_bsum[t];   // exclusive
}

__global__ __launch_bounds__(256) void k_offsets() {
    __shared__ int ws[8];
    int i = blockIdx.x * 256 + threadIdx.x;
    int deg = (i < NN) ? g_degi[i] : 0;
    int lane = threadIdx.x & 31, wid = threadIdx.x >> 5;
    int v = deg;
#pragma unroll
    for (int o = 1; o < 32; o <<= 1) {
        int t = __shfl_up_sync(0xFFFFFFFFu, v, o);
        if (lane >= o) v += t;
    }
    if (lane == 31) ws[wid] = v;
    __syncthreads();
    if (wid == 0 && lane < 8) {
        int w = ws[lane];
#pragma unroll
        for (int o = 1; o < 8; o <<= 1) {
            int t = __shfl_up_sync(0xFFu, w, o);
            if (lane >= o) w += t;
        }
        ws[lane] = w;
    }
    __syncthreads();
    int excl = v - deg + (wid > 0 ? ws[wid - 1] : 0) + g_boff[blockIdx.x];
    if (i < NN) {
        g_off[i] = excl;
        g_cur[i] = excl;
        g_dinv[i] = rsqrtf((float)(deg + 1));
    }
}

__global__ void k_csr_fill(const void* __restrict__ ei) {
    int e = blockIdx.x * blockDim.x + threadIdx.x;
    if (e >= NE) return;
    int s = read_idx(ei, e);
    int d = read_idx(ei, (long long)NE + e);
    s = min(max(s, 0), NN - 1);
    d = min(max(d, 0), NN - 1);
    int pos = atomicAdd(&g_cur[d], 1);
    float nrm = g_dinv[s] * g_dinv[d];
    g_edge[pos] = make_int2(s, __float_as_int(nrm));
}

// ---------------- fused layer 1: gather-agg(x_h,64) + HMMA GEMM W1 + relu -> H1(fp16) ----------------
#define LDA1 72    // halves (row = 144B)
__global__ __launch_bounds__(256)
void k_fused1(const float* __restrict__ bias) {
    __shared__ __half As[64 * LDA1];     // 9.2 KB
    __shared__ __half Wh[64 * 136];      // 17.4 KB

    const int tid = threadIdx.x;
    const int lane = tid & 31;
    const int w = tid >> 5;
    const int node_base = blockIdx.x * 64;
    const unsigned* __restrict__ Xu = (const unsigned*)g_xh;
    const int2* __restrict__ E = g_edge;
    unsigned* As_u = (unsigned*)As;

    // load W1 fp16 into padded smem [64][136]
#pragma unroll
    for (int it = 0; it < 4; ++it) {
        int idx = tid + it * 256;              // uint4 chunks: 1024 total
        int row = idx >> 4, ch = idx & 15;
        uint4 v = ((const uint4*)g_w1h)[idx];
        *(uint4*)&Wh[row * 136 + ch * 8] = v;
    }

    // phase 1: warp-per-node gather aggregation, unroll 4
    for (int j = w; j < 64; j += 8) {
        int node = node_base + j;
        float2 acc;
        if (node < NN) {
            float di = g_dinv[node];
            float sw = di * di;
            acc = h2f(Xu[node * 32 + lane]);
            acc.x *= sw; acc.y *= sw;
            int beg = g_off[node];
            int cnt = g_degi[node];
            int k = 0;
            for (; k + 4 <= cnt; k += 4) {
                int2 e0 = E[beg + k];
                int2 e1 = E[beg + k + 1];
                int2 e2 = E[beg + k + 2];
                int2 e3 = E[beg + k + 3];
                float2 v0 = h2f(Xu[e0.x * 32 + lane]);
                float2 v1 = h2f(Xu[e1.x * 32 + lane]);
                float2 v2 = h2f(Xu[e2.x * 32 + lane]);
                float2 v3 = h2f(Xu[e3.x * 32 + lane]);
                float w0 = __int_as_float(e0.y);
                float w1 = __int_as_float(e1.y);
                float w2 = __int_as_float(e2.y);
                float w3 = __int_as_float(e3.y);
                acc.x += w0 * v0.x + w1 * v1.x + w2 * v2.x + w3 * v3.x;
                acc.y += w0 * v0.y + w1 * v1.y + w2 * v2.y + w3 * v3.y;
            }
            for (; k < cnt; ++k) {
                int2 e0 = E[beg + k];
                float w0 = __int_as_float(e0.y);
                float2 v0 = h2f(Xu[e0.x * 32 + lane]);
                acc.x += w0 * v0.x;
                acc.y += w0 * v0.y;
            }
        } else {
            acc.x = 0.0f; acc.y = 0.0f;
        }
        __half2 h = __floats2half2_rn(acc.x, acc.y);
        As_u[j * (LDA1 / 2) + lane] = *(unsigned*)&h;
    }
    __syncthreads();

    // phase 2: HMMA GEMM (64x64) x (64x128)
    const int mt = w >> 1;
    const int nh = w & 1;
    float acc[8][4];
#pragma unroll
    for (int i = 0; i < 8; ++i)
#pragma unroll
        for (int jj = 0; jj < 4; ++jj) acc[i][jj] = 0.0f;

    mma_gemm_phase<C_IN, LDA1>(s2u(As), s2u(Wh), lane, mt, nh, acc);

    // epilogue: bias + relu -> fp16 store
    const int gid = lane >> 2, tig = lane & 3;
#pragma unroll
    for (int nt = 0; nt < 8; ++nt) {
        int col = nh * 64 + nt * 8 + tig * 2;
        float b0v = __ldg(&bias[col]);
        float b1v = __ldg(&bias[col + 1]);
        int r0 = node_base + mt * 16 + gid;
        int r1 = r0 + 8;
        if (r0 < NN) {
            __half2 h = __floats2half2_rn(fmaxf(acc[nt][0] + b0v, 0.0f),
                                          fmaxf(acc[nt][1] + b1v, 0.0f));
            ((unsigned*)g_h1h)[(size_t)r0 * 64 + (col >> 1)] = *(unsigned*)&h;
        }
        if (r1 < NN) {
            __half2 h = __floats2half2_rn(fmaxf(acc[nt][2] + b0v, 0.0f),
                                          fmaxf(acc[nt][3] + b1v, 0.0f));
            ((unsigned*)g_h1h)[(size_t)r1 * 64 + (col >> 1)] = *(unsigned*)&h;
        }
    }
}

// ---------------- fused layer 2: gather-agg(H1h,128) + HMMA GEMM W2 + relu + mean-pool ----------------
#define LDA2 136                    // halves (row = 272B)
#define F2_AS_B   (64 * LDA2 * 2)   // 17408
#define F2_W_B    (128 * 136 * 2)   // 34816
#define F2_SBAT_B (64 * 4)
#define F2_SMEM   (F2_AS_B + F2_W_B + F2_SBAT_B)   // 52480 (out[64][128] f32 overlays As+W)

__global__ __launch_bounds__(256)
void k_fused2(const float* __restrict__ bias, const void* __restrict__ batch) {
    extern __shared__ char smb[];
    __half* As = (__half*)smb;
    __half* Wh = (__half*)(smb + F2_AS_B);
    float*  out = (float*)smb;                       // reused after GEMM
    int*    sbat = (int*)(smb + F2_AS_B + F2_W_B);

    const int tid = threadIdx.x;
    const int lane = tid & 31;
    const int w = tid >> 5;
    const int node_base = blockIdx.x * 64;
    const int lim = min(64, NN - node_base);
    const uint2* __restrict__ Hu = (const uint2*)g_h1h;
    const int2* __restrict__ E = g_edge;
    uint2* As_u2 = (uint2*)As;

    if (tid < 64) {
        int n = node_base + tid;
        int g = 0;
        if (n < NN) g = read_idx(batch, n);
        sbat[tid] = min(max(g, 0), NG - 1);
    }

    // load W2 fp16 into padded smem [128][136]
#pragma unroll
    for (int it = 0; it < 8; ++it) {
        int idx = tid + it * 256;              // uint4 chunks: 2048 total
        int row = idx >> 4, ch = idx & 15;
        uint4 v = ((const uint4*)g_w2h)[idx];
        *(uint4*)&Wh[row * 136 + ch * 8] = v;
    }

    // phase 1: warp-per-node gather aggregation, unroll 4
    for (int j = w; j < 64; j += 8) {
        int node = node_base + j;
        float4 acc;
        if (node < NN) {
            float di = g_dinv[node];
            float sw = di * di;
            uint2 su = Hu[(size_t)node * 32 + lane];
            float2 sa = h2f(su.x), sb = h2f(su.y);
            acc = make_float4(sa.x * sw, sa.y * sw, sb.x * sw, sb.y * sw);
            int beg = g_off[node];
            int cnt = g_degi[node];
            int k = 0;
            for (; k + 4 <= cnt; k += 4) {
                int2 e0 = E[beg + k];
                int2 e1 = E[beg + k + 1];
                int2 e2 = E[beg + k + 2];
                int2 e3 = E[beg + k + 3];
                uint2 u0 = Hu[(size_t)e0.x * 32 + lane];
                uint2 u1 = Hu[(size_t)e1.x * 32 + lane];
                uint2 u2 = Hu[(size_t)e2.x * 32 + lane];
                uint2 u3 = Hu[(size_t)e3.x * 32 + lane];
                float w0 = __int_as_float(e0.y);
                float w1 = __int_as_float(e1.y);
                float w2 = __int_as_float(e2.y);
                float w3 = __int_as_float(e3.y);
                float2 a0 = h2f(u0.x), b0 = h2f(u0.y);
                float2 a1 = h2f(u1.x), b1 = h2f(u1.y);
                float2 a2 = h2f(u2.x), b2 = h2f(u2.y);
                float2 a3 = h2f(u3.x), b3 = h2f(u3.y);
                acc.x += w0 * a0.x + w1 * a1.x + w2 * a2.x + w3 * a3.x;
                acc.y += w0 * a0.y + w1 * a1.y + w2 * a2.y + w3 * a3.y;
                acc.z += w0 * b0.x + w1 * b1.x + w2 * b2.x + w3 * b3.x;
                acc.w += w0 * b0.y + w1 * b1.y + w2 * b2.y + w3 * b3.y;
            }
            for (; k < cnt; ++k) {
                int2 e0 = E[beg + k];
                float w0 = __int_as_float(e0.y);
                uint2 u0 = Hu[(size_t)e0.x * 32 + lane];
                float2 a0 = h2f(u0.x), b0 = h2f(u0.y);
                acc.x += w0 * a0.x;
                acc.y += w0 * a0.y;
                acc.z += w0 * b0.x;
                acc.w += w0 * b0.y;
            }
        } else {
            acc = make_float4(0.0f, 0.0f, 0.0f, 0.0f);
        }
        __half2 h0 = __floats2half2_rn(acc.x, acc.y);
        __half2 h1 = __floats2half2_rn(acc.z, acc.w);
        uint2 u;
        u.x = *(unsigned*)&h0;
        u.y = *(unsigned*)&h1;
        As_u2[j * (LDA2 / 4) + lane] = u;
    }
    __syncthreads();

    // phase 2: HMMA GEMM (64x128) x (128x128)
    const int mt = w >> 1;
    const int nh = w & 1;
    float acc[8][4];
#pragma unroll
    for (int i = 0; i < 8; ++i)
#pragma unroll
        for (int jj = 0; jj < 4; ++jj) acc[i][jj] = 0.0f;

    mma_gemm_phase<C_HID, LDA2>(s2u(As), s2u(Wh), lane, mt, nh, acc);
    __syncthreads();   // all reads of As/Wh done before overlaying `out`

    // phase 3: bias + relu into smem out[64][128]
    const int gid = lane >> 2, tig = lane & 3;
    const int r0l = mt * 16 + gid, r1l = r0l + 8;
#pragma unroll
    for (int nt = 0; nt < 8; ++nt) {
        int col = nh * 64 + nt * 8 + tig * 2;
        float b0v = __ldg(&bias[col]);
        float b1v = __ldg(&bias[col + 1]);
        out[r0l * 128 + col]     = fmaxf(acc[nt][0] + b0v, 0.0f);
        out[r0l * 128 + col + 1] = fmaxf(acc[nt][1] + b1v, 0.0f);
        out[r1l * 128 + col]     = fmaxf(acc[nt][2] + b0v, 0.0f);
        out[r1l * 128 + col + 1] = fmaxf(acc[nt][3] + b1v, 0.0f);
    }
    __syncthreads();

    // phase 4: per-column pooled reduction over sorted batch ids
    if (tid < 128 && lim > 0) {
        int c = tid;
        float accp = 0.0f;
        int g = sbat[0];
        for (int r = 0; r < lim; ++r) {
            int gb = sbat[r];
            if (gb != g) {
                atomicAdd(&g_pooled[g * C_HID + c], accp);
                g = gb; accp = 0.0f;
            }
            accp += out[r * 128 + c];
        }
        atomicAdd(&g_pooled[g * C_HID + c], accp);
    }
}

// ---------------- graph-size histogram ----------------
__global__ __launch_bounds__(256) void k_cnt(const void* __restrict__ batch) {
    __shared__ int h[NG];
    if (threadIdx.x < NG) h[threadIdx.x] = 0;
    __syncthreads();
    int n = blockIdx.x * 256 + threadIdx.x;
    if (n < NN) {
        int g = read_idx(batch, n);
        g = min(max(g, 0), NG - 1);
        atomicAdd(&h[g], 1);
    }
    __syncthreads();
    if (threadIdx.x < NG && h[threadIdx.x] > 0)
        atomicAdd(&g_cnt[threadIdx.x], (float)h[threadIdx.x]);
}

// ---------------- classifier head ----------------
__global__ void k_final(const float* __restrict__ Wc, const float* __restrict__ bc,
                        float* __restrict__ out) {
    int t = threadIdx.x;
    if (t >= NG * NC) return;
    int g = t / NC, c = t % NC;
    float inv = 1.0f / fmaxf(g_cnt[g], 1.0f);
    float s = 0.0f;
#pragma unroll 16
    for (int h = 0; h < C_HID; ++h)
        s += g_pooled[g * C_HID + h] * __ldg(&Wc[h * NC + c]);
    out[t] = s * inv + bc[c];
}

// ---------------- launch ----------------
extern "C" void kernel_launch(void* const* d_in, const int* in_sizes, int n_in,
                              void* d_out, int out_size) {
    const float* x = 0; const float* W1 = 0; const float* b1 = 0;
    const float* W2 = 0; const float* b2 = 0; const float* Wc = 0;
    const float* bc = 0; const void* ei = 0; const void* batch = 0;
    for (int i = 0; i < n_in; ++i) {
        int s = in_sizes[i];
        void* p = d_in[i];
        if      (s == NN * C_IN)     x  = (const float*)p;
        else if (s == C_IN * C_HID)  W1 = (const float*)p;
        else if (s == C_HID * C_HID) W2 = (const float*)p;
        else if (s == C_HID * NC)    Wc = (const float*)p;
        else if (s == NC)            bc = (const float*)p;
        else if (s == 2 * NE)        ei = p;
        else if (s == NN)            batch = p;
        else if (s == C_HID)         { if (!b1) b1 = (const float*)p; else b2 = (const float*)p; }
    }
    if (!b2) b2 = b1;
    float* out = (float*)d_out;
    (void)out_size;

    static int attr_done = 0;
    if (!attr_done) {
        cudaFuncSetAttribute(k_fused2, cudaFuncAttributeMaxDynamicSharedMemorySize, F2_SMEM);
        attr_done = 1;
    }

    const int T = 256;
    __half* w1h_p; cudaGetSymbolAddress((void**)&w1h_p, g_w1h);
    __half* w2h_p; cudaGetSymbolAddress((void**)&w2h_p, g_w2h);

    k_detect<<<1, 32>>>(ei);                              // 0
    k_init<<<NBLK, T>>>();                                // 1
    k_tohalf<<<(NN * C_IN / 4 + T - 1) / T, T>>>(x);      // 2
    k_edge_prep<<<(NE + T - 1) / T, T>>>(ei);             // 3
    k_whalf<<<16, T>>>(W1, w1h_p, C_IN * C_HID / 2);      // 4
    k_whalf<<<32, T>>>(W2, w2h_p, C_HID * C_HID / 2);     // 5
    k_blocksum<<<NBLK, T>>>();                            // 6
    k_bscan<<<1, 512>>>();                                // 7
    k_offsets<<<NBLK, T>>>();                             // 8
    k_csr_fill<<<(NE + T - 1) / T, T>>>(ei);              // 9
    k_cnt<<<NBLK, T>>>(batch);                            // 10

    k_fused1<<<NTILE, T>>>(b1);                           // 11
    k_fused2<<<NTILE, T, F2_SMEM>>>(b2, batch);           // 12

    k_final<<<1, 640>>>(Wc, bc, out);                     // 13
}

// round 11
// speedup vs baseline: 3.5305x; 1.0510x over previous
#include <cuda_runtime.h>
#include <cuda_fp16.h>

#define NN 100000
#define NE 1600000
#define C_IN 64
#define C_HID 128
#define NG 64
#define NC 10
#define NBLK ((NN + 255) / 256)   // 391
#define NTILE ((NN + 63) / 64)    // 1563

// ---------------- scratch (__device__ globals; no allocations) ----------------
static __device__ __align__(16) int    g_degi[NN];
static __device__ __align__(16) int    g_off[NN];
static __device__ __align__(16) int    g_cur[NN];
static __device__ __align__(16) float  g_dinv[NN];
static __device__ __align__(16) int    g_bsum[NBLK];
static __device__ __align__(16) int    g_boff[NBLK];
static __device__ __align__(16) int2   g_sd[NE];       // decoded {src, dst}
static __device__ __align__(16) int2   g_edge[NE];     // CSR payload: {src, norm-bits}
static __device__ __align__(16) __half g_xh[(size_t)NN * C_IN];    // 12.8 MB
static __device__ __align__(16) __half g_h1h[(size_t)NN * C_HID];  // 25.6 MB
static __device__ __align__(16) __half g_w1h[C_IN * C_HID];
static __device__ __align__(16) __half g_w2h[C_HID * C_HID];
static __device__ __align__(16) float  g_pooled[NG * C_HID];
static __device__ __align__(16) float  g_cnt[NG];
static __device__ int g_is64;

__device__ __forceinline__ int read_idx(const void* p, long long i) {
    if (g_is64) return (int)((const long long*)p)[i];
    return ((const int*)p)[i];
}
__device__ __forceinline__ float2 h2f(unsigned u) {
    __half2 h = *(__half2*)&u;
    return __half22float2(h);
}
__device__ __forceinline__ unsigned s2u(const void* p) {
    return (unsigned)__cvta_generic_to_shared(p);
}

// ---------------- mma / ldmatrix helpers ----------------
__device__ __forceinline__ void mma_f16(float c[4], unsigned a0, unsigned a1,
                                        unsigned a2, unsigned a3,
                                        unsigned b0, unsigned b1) {
    asm volatile(
        "mma.sync.aligned.m16n8k16.row.col.f32.f16.f16.f32 "
        "{%0,%1,%2,%3}, {%4,%5,%6,%7}, {%8,%9}, {%0,%1,%2,%3};"
        : "+f"(c[0]), "+f"(c[1]), "+f"(c[2]), "+f"(c[3])
        : "r"(a0), "r"(a1), "r"(a2), "r"(a3), "r"(b0), "r"(b1));
}
__device__ __forceinline__ void ldsm_x4(unsigned& r0, unsigned& r1, unsigned& r2,
                                        unsigned& r3, unsigned addr) {
    asm volatile("ldmatrix.sync.aligned.m8n8.x4.shared.b16 {%0,%1,%2,%3}, [%4];"
                 : "=r"(r0), "=r"(r1), "=r"(r2), "=r"(r3) : "r"(addr));
}
__device__ __forceinline__ void ldsm_x4_t(unsigned& r0, unsigned& r1, unsigned& r2,
                                          unsigned& r3, unsigned addr) {
    asm volatile("ldmatrix.sync.aligned.m8n8.x4.trans.shared.b16 {%0,%1,%2,%3}, [%4];"
                 : "=r"(r0), "=r"(r1), "=r"(r2), "=r"(r3) : "r"(addr));
}

// GEMM phase: acc[8][4] += As[mt*16..+16, 0..K) x W[0..K, nh*64..+64)
template<int K, int LDA>
__device__ __forceinline__ void mma_gemm_phase(unsigned asb, unsigned wb, int lane,
                                               int mt, int nh, float acc[8][4]) {
    const int m0 = mt * 16;
    unsigned a_base = asb + (((m0 + (lane & 15)) * LDA) + ((lane >> 4) << 3)) * 2;
    const int brow = (lane & 7) + (lane & 8);
    const int bcol = nh * 64 + ((lane & 16) >> 1);
#pragma unroll
    for (int k0 = 0; k0 < K; k0 += 16) {
        unsigned a0, a1, a2, a3;
        ldsm_x4(a0, a1, a2, a3, a_base + k0 * 2);
#pragma unroll
        for (int p = 0; p < 4; ++p) {
            unsigned b0, b1, b2, b3;
            unsigned baddr = wb + (((k0 + brow) * 136) + bcol + p * 16) * 2;
            ldsm_x4_t(b0, b1, b2, b3, baddr);
            mma_f16(acc[2 * p],     a0, a1, a2, a3, b0, b1);
            mma_f16(acc[2 * p + 1], a0, a1, a2, a3, b2, b3);
        }
    }
}

// ---------------- dtype detection ----------------
__global__ void k_detect(const void* __restrict__ ei) {
    if (threadIdx.x == 0) {
        const long long* p = (const long long*)ei;
        int ok64 = 1;
        for (int i = 0; i < 64; ++i) {
            long long v = p[i];
            if (v < 0 || v >= NN) { ok64 = 0; break; }
        }
        g_is64 = ok64;
    }
}

// ---------------- init (zero ONLY — no accumulation in the same grid) ----------------
__global__ __launch_bounds__(256) void k_init() {
    int t = blockIdx.x * 256 + threadIdx.x;
    if (t < NN) g_degi[t] = 0;
    if (t < NG * C_HID) g_pooled[t] = 0.0f;
    if (t < NG) g_cnt[t] = 0.0f;
}

// ---------------- fp16 conversions: x, W1, W2 in one kernel ----------------
#define NT_X  (NN * C_IN / 4)          // float4 items: 1,600,000
#define NT_W1 (C_IN * C_HID / 2)       // half2 items:  4096
#define NT_W2 (C_HID * C_HID / 2)      // half2 items:  8192
__global__ __launch_bounds__(256)
void k_convert(const float* __restrict__ X, const float* __restrict__ W1,
               const float* __restrict__ W2) {
    int i = blockIdx.x * 256 + threadIdx.x;
    if (i < NT_X) {
        float4 v = ((const float4*)X)[i];
        __half2 a = __floats2half2_rn(v.x, v.y);
        __half2 b = __floats2half2_rn(v.z, v.w);
        uint2 u;
        u.x = *(unsigned*)&a;
        u.y = *(unsigned*)&b;
        ((uint2*)g_xh)[i] = u;
    } else if (i < NT_X + NT_W1) {
        int j = i - NT_X;
        float2 v = ((const float2*)W1)[j];
        ((__half2*)g_w1h)[j] = __floats2half2_rn(v.x, v.y);
    } else if (i < NT_X + NT_W1 + NT_W2) {
        int j = i - NT_X - NT_W1;
        float2 v = ((const float2*)W2)[j];
        ((__half2*)g_w2h)[j] = __floats2half2_rn(v.x, v.y);
    }
}

// ---------------- edge prep: decode int64/int32 once, count degrees ----------------
__global__ void k_edge_prep(const void* __restrict__ ei) {
    int e = blockIdx.x * blockDim.x + threadIdx.x;
    if (e >= NE) return;
    int s = read_idx(ei, e);
    int d = read_idx(ei, (long long)NE + e);
    s = min(max(s, 0), NN - 1);
    d = min(max(d, 0), NN - 1);
    g_sd[e] = make_int2(s, d);
    atomicAdd(&g_degi[d], 1);
}

// ---- block sums for scan + batch histogram (g_cnt zeroed in EARLIER kernel) ----
__global__ __launch_bounds__(256) void k_blocksum(const void* __restrict__ batch) {
    __shared__ int ws[8];
    __shared__ int h[NG];
    if (threadIdx.x < NG) h[threadIdx.x] = 0;
    int i = blockIdx.x * 256 + threadIdx.x;
    int v = (i < NN) ? g_degi[i] : 0;
    int lane = threadIdx.x & 31, wid = threadIdx.x >> 5;
#pragma unroll
    for (int o = 16; o > 0; o >>= 1) v += __shfl_down_sync(0xFFFFFFFFu, v, o);
    if (lane == 0) ws[wid] = v;
    __syncthreads();
    if (threadIdx.x == 0) {
        int s = 0;
#pragma unroll
        for (int w = 0; w < 8; ++w) s += ws[w];
        g_bsum[blockIdx.x] = s;
    }
    // batch histogram
    if (i < NN) {
        int g = read_idx(batch, i);
        g = min(max(g, 0), NG - 1);
        atomicAdd(&h[g], 1);
    }
    __syncthreads();
    if (threadIdx.x < NG && h[threadIdx.x] > 0)
        atomicAdd(&g_cnt[threadIdx.x], (float)h[threadIdx.x]);
}

__global__ __launch_bounds__(512) void k_bscan() {
    __shared__ int sh[512];
    int t = threadIdx.x;
    sh[t] = (t < NBLK) ? g_bsum[t] : 0;
    __syncthreads();
#pragma unroll
    for (int o = 1; o < 512; o <<= 1) {
        int v = (t >= o) ? sh[t - o] : 0;
        __syncthreads();
        sh[t] += v;
        __syncthreads();
    }
    if (t < NBLK) g_boff[t] = sh[t] - g_bsum[t];   // exclusive
}

__global__ __launch_bounds__(256) void k_offsets() {
    __shared__ int ws[8];
    int i = blockIdx.x * 256 + threadIdx.x;
    int deg = (i < NN) ? g_degi[i] : 0;
    int lane = threadIdx.x & 31, wid = threadIdx.x >> 5;
    int v = deg;
#pragma unroll
    for (int o = 1; o < 32; o <<= 1) {
        int t = __shfl_up_sync(0xFFFFFFFFu, v, o);
        if (lane >= o) v += t;
    }
    if (lane == 31) ws[wid] = v;
    __syncthreads();
    if (wid == 0 && lane < 8) {
        int w = ws[lane];
#pragma unroll
        for (int o = 1; o < 8; o <<= 1) {
            int t = __shfl_up_sync(0xFFu, w, o);
            if (lane >= o) w += t;
        }
        ws[lane] = w;
    }
    __syncthreads();
    int excl = v - deg + (wid > 0 ? ws[wid - 1] : 0) + g_boff[blockIdx.x];
    if (i < NN) {
        g_off[i] = excl;
        g_cur[i] = excl;
        g_dinv[i] = rsqrtf((float)(deg + 1));
    }
}

// fill CSR payload from decoded pairs
__global__ void k_csr_fill() {
    int e = blockIdx.x * blockDim.x + threadIdx.x;
    if (e >= NE) return;
    int2 sd = g_sd[e];
    int pos = atomicAdd(&g_cur[sd.y], 1);
    float nrm = g_dinv[sd.x] * g_dinv[sd.y];
    g_edge[pos] = make_int2(sd.x, __float_as_int(nrm));
}

// ---------------- fused layer 1: gather-agg(x_h,64) + HMMA GEMM W1 + relu -> H1(fp16) ----------------
#define LDA1 72    // halves (row = 144B)
__global__ __launch_bounds__(256)
void k_fused1(const float* __restrict__ bias) {
    __shared__ __half As[64 * LDA1];     // 9.2 KB
    __shared__ __half Wh[64 * 136];      // 17.4 KB

    const int tid = threadIdx.x;
    const int lane = tid & 31;
    const int w = tid >> 5;
    const int node_base = blockIdx.x * 64;
    const unsigned* __restrict__ Xu = (const unsigned*)g_xh;
    const int2* __restrict__ E = g_edge;
    unsigned* As_u = (unsigned*)As;

    // load W1 fp16 into padded smem [64][136]
#pragma unroll
    for (int it = 0; it < 4; ++it) {
        int idx = tid + it * 256;              // uint4 chunks: 1024 total
        int row = idx >> 4, ch = idx & 15;
        uint4 v = ((const uint4*)g_w1h)[idx];
        *(uint4*)&Wh[row * 136 + ch * 8] = v;
    }

    // phase 1: warp-per-node gather aggregation, unroll 4
    for (int j = w; j < 64; j += 8) {
        int node = node_base + j;
        float2 acc;
        if (node < NN) {
            float di = g_dinv[node];
            float sw = di * di;
            acc = h2f(Xu[node * 32 + lane]);
            acc.x *= sw; acc.y *= sw;
            int beg = g_off[node];
            int cnt = g_degi[node];
            int k = 0;
            for (; k + 4 <= cnt; k += 4) {
                int2 e0 = E[beg + k];
                int2 e1 = E[beg + k + 1];
                int2 e2 = E[beg + k + 2];
                int2 e3 = E[beg + k + 3];
                float2 v0 = h2f(Xu[e0.x * 32 + lane]);
                float2 v1 = h2f(Xu[e1.x * 32 + lane]);
                float2 v2 = h2f(Xu[e2.x * 32 + lane]);
                float2 v3 = h2f(Xu[e3.x * 32 + lane]);
                float w0 = __int_as_float(e0.y);
                float w1 = __int_as_float(e1.y);
                float w2 = __int_as_float(e2.y);
                float w3 = __int_as_float(e3.y);
                acc.x += w0 * v0.x + w1 * v1.x + w2 * v2.x + w3 * v3.x;
                acc.y += w0 * v0.y + w1 * v1.y + w2 * v2.y + w3 * v3.y;
            }
            for (; k < cnt; ++k) {
                int2 e0 = E[beg + k];
                float w0 = __int_as_float(e0.y);
                float2 v0 = h2f(Xu[e0.x * 32 + lane]);
                acc.x += w0 * v0.x;
                acc.y += w0 * v0.y;
            }
        } else {
            acc.x = 0.0f; acc.y = 0.0f;
        }
        __half2 h = __floats2half2_rn(acc.x, acc.y);
        As_u[j * (LDA1 / 2) + lane] = *(unsigned*)&h;
    }
    __syncthreads();

    // phase 2: HMMA GEMM (64x64) x (64x128)
    const int mt = w >> 1;
    const int nh = w & 1;
    float acc[8][4];
#pragma unroll
    for (int i = 0; i < 8; ++i)
#pragma unroll
        for (int jj = 0; jj < 4; ++jj) acc[i][jj] = 0.0f;

    mma_gemm_phase<C_IN, LDA1>(s2u(As), s2u(Wh), lane, mt, nh, acc);

    // epilogue: bias + relu -> fp16 store
    const int gid = lane >> 2, tig = lane & 3;
#pragma unroll
    for (int nt = 0; nt < 8; ++nt) {
        int col = nh * 64 + nt * 8 + tig * 2;
        float b0v = __ldg(&bias[col]);
        float b1v = __ldg(&bias[col + 1]);
        int r0 = node_base + mt * 16 + gid;
        int r1 = r0 + 8;
        if (r0 < NN) {
            __half2 h = __floats2half2_rn(fmaxf(acc[nt][0] + b0v, 0.0f),
                                          fmaxf(acc[nt][1] + b1v, 0.0f));
            ((unsigned*)g_h1h)[(size_t)r0 * 64 + (col >> 1)] = *(unsigned*)&h;
        }
        if (r1 < NN) {
            __half2 h = __floats2half2_rn(fmaxf(acc[nt][2] + b0v, 0.0f),
                                          fmaxf(acc[nt][3] + b1v, 0.0f));
            ((unsigned*)g_h1h)[(size_t)r1 * 64 + (col >> 1)] = *(unsigned*)&h;
        }
    }
}

// ---------------- fused layer 2: gather-agg(H1h,128) + HMMA GEMM W2 + relu + mean-pool ----------------
#define LDA2 136                    // halves (row = 272B)
#define F2_AS_B   (64 * LDA2 * 2)   // 17408
#define F2_W_B    (128 * 136 * 2)   // 34816
#define F2_SBAT_B (64 * 4)
#define F2_SMEM   (F2_AS_B + F2_W_B + F2_SBAT_B)   // 52480

__global__ __launch_bounds__(256)
void k_fused2(const float* __restrict__ bias, const void* __restrict__ batch) {
    extern __shared__ char smb[];
    __half* As = (__half*)smb;
    __half* Wh = (__half*)(smb + F2_AS_B);
    float*  out = (float*)smb;                       // reused after GEMM
    int*    sbat = (int*)(smb + F2_AS_B + F2_W_B);

    const int tid = threadIdx.x;
    const int lane = tid & 31;
    const int w = tid >> 5;
    const int node_base = blockIdx.x * 64;
    const int lim = min(64, NN - node_base);
    const uint2* __restrict__ Hu = (const uint2*)g_h1h;
    const int2* __restrict__ E = g_edge;
    uint2* As_u2 = (uint2*)As;

    if (tid < 64) {
        int n = node_base + tid;
        int g = 0;
        if (n < NN) g = read_idx(batch, n);
        sbat[tid] = min(max(g, 0), NG - 1);
    }

    // load W2 fp16 into padded smem [128][136]
#pragma unroll
    for (int it = 0; it < 8; ++it) {
        int idx = tid + it * 256;              // uint4 chunks: 2048 total
        int row = idx >> 4, ch = idx & 15;
        uint4 v = ((const uint4*)g_w2h)[idx];
        *(uint4*)&Wh[row * 136 + ch * 8] = v;
    }

    // phase 1: warp-per-node gather aggregation, unroll 4
    for (int j = w; j < 64; j += 8) {
        int node = node_base + j;
        float4 acc;
        if (node < NN) {
            float di = g_dinv[node];
            float sw = di * di;
            uint2 su = Hu[(size_t)node * 32 + lane];
            float2 sa = h2f(su.x), sb = h2f(su.y);
            acc = make_float4(sa.x * sw, sa.y * sw, sb.x * sw, sb.y * sw);
            int beg = g_off[node];
            int cnt = g_degi[node];
            int k = 0;
            for (; k + 4 <= cnt; k += 4) {
                int2 e0 = E[beg + k];
                int2 e1 = E[beg + k + 1];
                int2 e2 = E[beg + k + 2];
                int2 e3 = E[beg + k + 3];
                uint2 u0 = Hu[(size_t)e0.x * 32 + lane];
                uint2 u1 = Hu[(size_t)e1.x * 32 + lane];
                uint2 u2 = Hu[(size_t)e2.x * 32 + lane];
                uint2 u3 = Hu[(size_t)e3.x * 32 + lane];
                float w0 = __int_as_float(e0.y);
                float w1 = __int_as_float(e1.y);
                float w2 = __int_as_float(e2.y);
                float w3 = __int_as_float(e3.y);
                float2 a0 = h2f(u0.x), b0 = h2f(u0.y);
                float2 a1 = h2f(u1.x), b1 = h2f(u1.y);
                float2 a2 = h2f(u2.x), b2 = h2f(u2.y);
                float2 a3 = h2f(u3.x), b3 = h2f(u3.y);
                acc.x += w0 * a0.x + w1 * a1.x + w2 * a2.x + w3 * a3.x;
                acc.y += w0 * a0.y + w1 * a1.y + w2 * a2.y + w3 * a3.y;
                acc.z += w0 * b0.x + w1 * b1.x + w2 * b2.x + w3 * b3.x;
                acc.w += w0 * b0.y + w1 * b1.y + w2 * b2.y + w3 * b3.y;
            }
            for (; k < cnt; ++k) {
                int2 e0 = E[beg + k];
                float w0 = __int_as_float(e0.y);
                uint2 u0 = Hu[(size_t)e0.x * 32 + lane];
                float2 a0 = h2f(u0.x), b0 = h2f(u0.y);
                acc.x += w0 * a0.x;
                acc.y += w0 * a0.y;
                acc.z += w0 * b0.x;
                acc.w += w0 * b0.y;
            }
        } else {
            acc = make_float4(0.0f, 0.0f, 0.0f, 0.0f);
        }
        __half2 h0 = __floats2half2_rn(acc.x, acc.y);
        __half2 h1 = __floats2half2_rn(acc.z, acc.w);
        uint2 u;
        u.x = *(unsigned*)&h0;
        u.y = *(unsigned*)&h1;
        As_u2[j * (LDA2 / 4) + lane] = u;
    }
    __syncthreads();

    // phase 2: HMMA GEMM (64x128) x (128x128)
    const int mt = w >> 1;
    const int nh = w & 1;
    float acc[8][4];
#pragma unroll
    for (int i = 0; i < 8; ++i)
#pragma unroll
        for (int jj = 0; jj < 4; ++jj) acc[i][jj] = 0.0f;

    mma_gemm_phase<C_HID, LDA2>(s2u(As), s2u(Wh), lane, mt, nh, acc);
    __syncthreads();   // all reads of As/Wh done before overlaying `out`

    // phase 3: bias + relu into smem out[64][128]
    const int gid = lane >> 2, tig = lane & 3;
    const int r0l = mt * 16 + gid, r1l = r0l + 8;
#pragma unroll
    for (int nt = 0; nt < 8; ++nt) {
        int col = nh * 64 + nt * 8 + tig * 2;
        float b0v = __ldg(&bias[col]);
        float b1v = __ldg(&bias[col + 1]);
        out[r0l * 128 + col]     = fmaxf(acc[nt][0] + b0v, 0.0f);
        out[r0l * 128 + col + 1] = fmaxf(acc[nt][1] + b1v, 0.0f);
        out[r1l * 128 + col]     = fmaxf(acc[nt][2] + b0v, 0.0f);
        out[r1l * 128 + col + 1] = fmaxf(acc[nt][3] + b1v, 0.0f);
    }
    __syncthreads();

    // phase 4: per-column pooled reduction over sorted batch ids
    if (tid < 128 && lim > 0) {
        int c = tid;
        float accp = 0.0f;
        int g = sbat[0];
        for (int r = 0; r < lim; ++r) {
            int gb = sbat[r];
            if (gb != g) {
                atomicAdd(&g_pooled[g * C_HID + c], accp);
                g = gb; accp = 0.0f;
            }
            accp += out[r * 128 + c];
        }
        atomicAdd(&g_pooled[g * C_HID + c], accp);
    }
}

// ---------------- classifier head: one block per graph, warp-reduced dots ----------------
__global__ __launch_bounds__(32) void k_final(const float* __restrict__ Wc,
                                              const float* __restrict__ bc,
                                              float* __restrict__ out) {
    int g = blockIdx.x;
    int lane = threadIdx.x;
    float inv = 1.0f / fmaxf(g_cnt[g], 1.0f);
    float p[4];
#pragma unroll
    for (int i = 0; i < 4; ++i) p[i] = g_pooled[g * C_HID + i * 32 + lane];
#pragma unroll
    for (int c = 0; c < NC; ++c) {
        float s = 0.0f;
#pragma unroll
        for (int i = 0; i < 4; ++i)
            s += p[i] * __ldg(&Wc[(i * 32 + lane) * NC + c]);
#pragma unroll
        for (int o = 16; o > 0; o >>= 1)
            s += __shfl_down_sync(0xFFFFFFFFu, s, o);
        if (lane == 0) out[g * NC + c] = s * inv + bc[c];
    }
}

// ---------------- launch ----------------
extern "C" void kernel_launch(void* const* d_in, const int* in_sizes, int n_in,
                              void* d_out, int out_size) {
    const float* x = 0; const float* W1 = 0; const float* b1 = 0;
    const float* W2 = 0; const float* b2 = 0; const float* Wc = 0;
    const float* bc = 0; const void* ei = 0; const void* batch = 0;
    for (int i = 0; i < n_in; ++i) {
        int s = in_sizes[i];
        void* p = d_in[i];
        if      (s == NN * C_IN)     x  = (const float*)p;
        else if (s == C_IN * C_HID)  W1 = (const float*)p;
        else if (s == C_HID * C_HID) W2 = (const float*)p;
        else if (s == C_HID * NC)    Wc = (const float*)p;
        else if (s == NC)            bc = (const float*)p;
        else if (s == 2 * NE)        ei = p;
        else if (s == NN)            batch = p;
        else if (s == C_HID)         { if (!b1) b1 = (const float*)p; else b2 = (const float*)p; }
    }
    if (!b2) b2 = b1;
    float* out = (float*)d_out;
    (void)out_size;

    static int attr_done = 0;
    if (!attr_done) {
        cudaFuncSetAttribute(k_fused2, cudaFuncAttributeMaxDynamicSharedMemorySize, F2_SMEM);
        attr_done = 1;
    }

    const int T = 256;
    const int CVT_BLKS = (NT_X + NT_W1 + NT_W2 + T - 1) / T;

    k_detect<<<1, 32>>>(ei);                              // 0
    k_init<<<NBLK, T>>>();                                // 1
    k_convert<<<CVT_BLKS, T>>>(x, W1, W2);                // 2
    k_edge_prep<<<(NE + T - 1) / T, T>>>(ei);             // 3
    k_blocksum<<<NBLK, T>>>(batch);                       // 4 (scan sums + batch histogram)
    k_bscan<<<1, 512>>>();                                // 5
    k_offsets<<<NBLK, T>>>();                             // 6
    k_csr_fill<<<(NE + T - 1) / T, T>>>();                // 7

    k_fused1<<<NTILE, T>>>(b1);                           // 8
    k_fused2<<<NTILE, T, F2_SMEM>>>(b2, batch);           // 9

    k_final<<<NG, 32>>>(Wc, bc, out);                     // 10
}